// round 2
// baseline (speedup 1.0000x reference)
#include <cuda_runtime.h>
#include <cuda_bf16.h>

#define BB 4
#define NN 8192
#define KK 16
#define CC 128
#define TT 3
#define BN_ (BB*NN)          // 32768 points
#define CE 131               // 3 + C

// ---------------- scratch (device globals; no allocation in kernel_launch) ----------------
__device__ float g_featA[BN_*CC];
__device__ float g_featB[BN_*CC];
__device__ float g_center[BN_*3];
__device__ float g_offW1t[CC*CC];          // [i][j] = off_W1[j][i]
__device__ float g_edgeW1t[TT*CE*CC];      // row i<128 -> src col 3+i (feat), i>=128 -> src col i-128 (rel_pos)
__device__ float g_edgeW2t[TT*CC*CC];
__device__ float g_updW1t[TT*2*CC*CC];     // [i][j], i in [0,256): 0..127 agg, 128..255 feat
__device__ float g_updW2t[TT*CC*CC];

// ---------------- prep: transpose / reorder weights ----------------
__global__ void prep_kernel(const float* __restrict__ off_W1,
                            const float* __restrict__ edge_W1,
                            const float* __restrict__ edge_W2,
                            const float* __restrict__ upd_W1,
                            const float* __restrict__ upd_W2) {
    int tid0 = blockIdx.x * blockDim.x + threadIdx.x;
    int stride = gridDim.x * blockDim.x;

    for (int x = tid0; x < CC*CC; x += stride) {
        int i = x >> 7, j = x & 127;
        g_offW1t[x] = off_W1[j*CC + i];
    }
    for (int x = tid0; x < TT*CE*CC; x += stride) {
        int t = x / (CE*CC); int r = x - t*(CE*CC);
        int i = r >> 7, j = r & 127;
        int src_i = (i < CC) ? (i + 3) : (i - CC);
        g_edgeW1t[x] = edge_W1[(t*CC + j)*CE + src_i];
    }
    for (int x = tid0; x < TT*CC*CC; x += stride) {
        int t = x >> 14; int r = x & 16383;
        int i = r >> 7, j = r & 127;
        g_edgeW2t[x] = edge_W2[(t*CC + j)*CC + i];
    }
    for (int x = tid0; x < TT*2*CC*CC; x += stride) {
        int t = x / (2*CC*CC); int r = x - t*(2*CC*CC);
        int i = r >> 7, j = r & 127;
        g_updW1t[x] = upd_W1[(t*CC + j)*(2*CC) + i];
    }
    for (int x = tid0; x < TT*CC*CC; x += stride) {
        int t = x >> 14; int r = x & 16383;
        int i = r >> 7, j = r & 127;
        g_updW2t[x] = upd_W2[(t*CC + j)*CC + i];
    }
}

// ---------------- offset MLP: center = xyz + Lin(relu(Lin(feat))) ----------------
__global__ __launch_bounds__(128) void offset_kernel(
    const float* __restrict__ feat, const float* __restrict__ xyz,
    const float* __restrict__ b1, const float* __restrict__ W2,
    const float* __restrict__ b2) {
    const int P = 8;
    __shared__ __align__(16) float fs[P][CC];
    __shared__ __align__(16) float hs[P][CC];
    int tid = threadIdx.x;
    int p0 = blockIdx.x * P;

    #pragma unroll
    for (int p = 0; p < P; p++) fs[p][tid] = feat[(p0+p)*CC + tid];
    __syncthreads();

    float acc[P];
    float bb = b1[tid];
    #pragma unroll
    for (int p = 0; p < P; p++) acc[p] = bb;

    for (int m = 0; m < CC/4; m++) {
        float w0 = g_offW1t[(4*m+0)*CC + tid];
        float w1 = g_offW1t[(4*m+1)*CC + tid];
        float w2 = g_offW1t[(4*m+2)*CC + tid];
        float w3 = g_offW1t[(4*m+3)*CC + tid];
        #pragma unroll
        for (int p = 0; p < P; p++) {
            float4 f = *(const float4*)&fs[p][4*m];
            acc[p] += w0*f.x + w1*f.y + w2*f.z + w3*f.w;
        }
    }
    #pragma unroll
    for (int p = 0; p < P; p++) hs[p][tid] = fmaxf(acc[p], 0.f);
    __syncthreads();

    if (tid < P*3) {
        int p = tid / 3, d = tid - 3*p;
        float s = b2[d];
        for (int i = 0; i < CC; i++) s += hs[p][i] * W2[d*CC + i];
        int g = p0 + p;
        g_center[g*3 + d] = xyz[g*3 + d] + s;
    }
}

// ---------------- edge MLP + max-agg + update MLP + residual ----------------
__global__ __launch_bounds__(128) void edge_upd_kernel(
    const float* __restrict__ feat_src, const float* __restrict__ xyz,
    const int* __restrict__ knn,
    const float* __restrict__ eb1, const float* __restrict__ eb2,
    const float* __restrict__ ub1, const float* __restrict__ ub2,
    int t, float* __restrict__ feat_dst) {
    const int P = 2, R = P*KK;   // 32 rows
    __shared__ __align__(16) float es[R][132];   // [feat(128), rel_pos(3), pad]
    __shared__ __align__(16) float us[P][2*CC];  // [agg(128), feat(128)] per point
    __shared__ int   idx_s[R];
    __shared__ float cs[P][3];

    int tid = threadIdx.x;
    int p0 = blockIdx.x * P;
    int base = (p0 >> 13) << 13;                 // batch base row (N=8192)

    const float* eW1t = g_edgeW1t + t*(CE*CC);
    const float* eW2t = g_edgeW2t + t*(CC*CC);
    const float* uW1t = g_updW1t  + t*(2*CC*CC);
    const float* uW2t = g_updW2t  + t*(CC*CC);

    if (tid < R) idx_s[tid] = knn[p0*KK + tid];
    if (tid < P*3) { int p = tid/3, d = tid - 3*p; cs[p][d] = g_center[(p0+p)*3 + d]; }
    __syncthreads();

    // gather neighbor features + center-point features
    #pragma unroll
    for (int r = 0; r < R; r++)
        es[r][tid] = feat_src[(base + idx_s[r])*CC + tid];
    us[0][CC + tid] = feat_src[ p0     *CC + tid];
    us[1][CC + tid] = feat_src[(p0+1)  *CC + tid];
    if (tid < 3*R) {
        int r = tid / 3, d = tid - 3*r;
        es[r][CC + d] = xyz[(base + idx_s[r])*3 + d] - cs[r >> 4][d];
    }
    __syncthreads();

    // ---- edge layer 1: (32 x 131) @ (131 x 128) ----
    float acc[R];
    {
        float bb = eb1[tid];
        #pragma unroll
        for (int r = 0; r < R; r++) acc[r] = bb;
    }
    for (int m = 0; m < CC/4; m++) {
        float w0 = eW1t[(4*m+0)*CC + tid];
        float w1 = eW1t[(4*m+1)*CC + tid];
        float w2 = eW1t[(4*m+2)*CC + tid];
        float w3 = eW1t[(4*m+3)*CC + tid];
        #pragma unroll
        for (int r = 0; r < R; r++) {
            float4 e = *(const float4*)&es[r][4*m];
            acc[r] += w0*e.x + w1*e.y + w2*e.z + w3*e.w;
        }
    }
    #pragma unroll
    for (int i = CC; i < CE; i++) {
        float w = eW1t[i*CC + tid];
        #pragma unroll
        for (int r = 0; r < R; r++) acc[r] += w * es[r][i];
    }
    __syncthreads();
    #pragma unroll
    for (int r = 0; r < R; r++) es[r][tid] = fmaxf(acc[r], 0.f);
    __syncthreads();

    // ---- edge layer 2: (32 x 128) @ (128 x 128) ----
    {
        float bb = eb2[tid];
        #pragma unroll
        for (int r = 0; r < R; r++) acc[r] = bb;
    }
    for (int m = 0; m < CC/4; m++) {
        float w0 = eW2t[(4*m+0)*CC + tid];
        float w1 = eW2t[(4*m+1)*CC + tid];
        float w2 = eW2t[(4*m+2)*CC + tid];
        float w3 = eW2t[(4*m+3)*CC + tid];
        #pragma unroll
        for (int r = 0; r < R; r++) {
            float4 e = *(const float4*)&es[r][4*m];
            acc[r] += w0*e.x + w1*e.y + w2*e.z + w3*e.w;
        }
    }

    // ---- max over K neighbors ----
    float agg0 = acc[0];
    #pragma unroll
    for (int k = 1; k < KK; k++) agg0 = fmaxf(agg0, acc[k]);
    float agg1 = acc[KK];
    #pragma unroll
    for (int k = 1; k < KK; k++) agg1 = fmaxf(agg1, acc[KK + k]);
    us[0][tid] = agg0;
    us[1][tid] = agg1;
    __syncthreads();

    // ---- update layer 1: (2 x 256) @ (256 x 128) ----
    float ua0 = ub1[tid], ua1 = ua0;
    for (int m = 0; m < (2*CC)/4; m++) {
        float w0 = uW1t[(4*m+0)*CC + tid];
        float w1 = uW1t[(4*m+1)*CC + tid];
        float w2 = uW1t[(4*m+2)*CC + tid];
        float w3 = uW1t[(4*m+3)*CC + tid];
        float4 a = *(const float4*)&us[0][4*m];
        ua0 += w0*a.x + w1*a.y + w2*a.z + w3*a.w;
        float4 b = *(const float4*)&us[1][4*m];
        ua1 += w0*b.x + w1*b.y + w2*b.z + w3*b.w;
    }
    float f0 = us[0][CC + tid];
    float f1 = us[1][CC + tid];
    __syncthreads();
    us[0][tid] = fmaxf(ua0, 0.f);
    us[1][tid] = fmaxf(ua1, 0.f);
    __syncthreads();

    // ---- update layer 2 + residual ----
    float o0 = ub2[tid], o1 = o0;
    for (int m = 0; m < CC/4; m++) {
        float w0 = uW2t[(4*m+0)*CC + tid];
        float w1 = uW2t[(4*m+1)*CC + tid];
        float w2 = uW2t[(4*m+2)*CC + tid];
        float w3 = uW2t[(4*m+3)*CC + tid];
        float4 a = *(const float4*)&us[0][4*m];
        o0 += w0*a.x + w1*a.y + w2*a.z + w3*a.w;
        float4 b = *(const float4*)&us[1][4*m];
        o1 += w0*b.x + w1*b.y + w2*b.z + w3*b.w;
    }
    feat_dst[ p0   *CC + tid] = f0 + o0;
    feat_dst[(p0+1)*CC + tid] = f1 + o1;
}

// ---------------- launch ----------------
extern "C" void kernel_launch(void* const* d_in, const int* in_sizes, int n_in,
                              void* d_out, int out_size) {
    const float* xyz      = (const float*)d_in[0];
    const float* features = (const float*)d_in[1];
    const int*   knn      = (const int*)  d_in[2];
    const float* off_W1   = (const float*)d_in[3];
    const float* off_b1   = (const float*)d_in[4];
    const float* off_W2   = (const float*)d_in[5];
    const float* off_b2   = (const float*)d_in[6];
    const float* edge_W1  = (const float*)d_in[7];
    const float* edge_b1  = (const float*)d_in[8];
    const float* edge_W2  = (const float*)d_in[9];
    const float* edge_b2  = (const float*)d_in[10];
    const float* upd_W1   = (const float*)d_in[11];
    const float* upd_b1   = (const float*)d_in[12];
    const float* upd_W2   = (const float*)d_in[13];
    const float* upd_b2   = (const float*)d_in[14];
    float* out = (float*)d_out;

    float *featA, *featB;
    cudaGetSymbolAddress((void**)&featA, g_featA);
    cudaGetSymbolAddress((void**)&featB, g_featB);

    prep_kernel<<<256, 256>>>(off_W1, edge_W1, edge_W2, upd_W1, upd_W2);

    const float* src = features;
    for (int t = 0; t < TT; t++) {
        float* dst = (t == TT-1) ? out : ((t == 0) ? featA : featB);
        offset_kernel<<<BN_/8, 128>>>(src, xyz, off_b1, off_W2, off_b2);
        edge_upd_kernel<<<BN_/2, 128>>>(src, xyz, knn,
                                        edge_b1 + t*CC, edge_b2 + t*CC,
                                        upd_b1  + t*CC, upd_b2  + t*CC,
                                        t, dst);
        src = dst;
    }
}

// round 6
// speedup vs baseline: 3.8040x; 3.8040x over previous
#include <cuda_runtime.h>
#include <cuda_bf16.h>
#include <cstdint>

#define BB 4
#define NN 8192
#define KK 16
#define CC 128
#define TT 3
#define BN_ (BB*NN)          // 32768 points
#define CE 131               // 3 + C
#define NTILES (BN_/8)       // 4096 edge tiles (8 points x 16 nbrs = 128 rows)
#define ES 132               // padded row stride (floats) -> conflict-free frags

// ---------------- device scratch ----------------
__device__ __align__(16) float g_featA[BN_*CC];
__device__ __align__(16) float g_featB[BN_*CC];
__device__ __align__(16) float g_agg[BN_*CC];
__device__ float  g_center[BN_*3];
__device__ float  g_offW1t[CC*CC];

// ---------------- helpers ----------------
__device__ __forceinline__ float f2tf(float x) {
    uint32_t u; asm("cvt.rna.tf32.f32 %0, %1;" : "=r"(u) : "f"(x));
    return __uint_as_float(u);
}
__device__ __forceinline__ float4 f2tf4(float4 v) {
    v.x = f2tf(v.x); v.y = f2tf(v.y); v.z = f2tf(v.z); v.w = f2tf(v.w);
    return v;
}
// m16n8k8 tf32 mma, acc += A*B
__device__ __forceinline__ void mma8(float* c, uint32_t a0, uint32_t a1,
                                     uint32_t a2, uint32_t a3,
                                     uint32_t b0, uint32_t b1) {
    asm volatile(
        "mma.sync.aligned.m16n8k8.row.col.f32.tf32.tf32.f32 "
        "{%0,%1,%2,%3}, {%4,%5,%6,%7}, {%8,%9}, {%0,%1,%2,%3};"
        : "+f"(c[0]), "+f"(c[1]), "+f"(c[2]), "+f"(c[3])
        : "r"(a0), "r"(a1), "r"(a2), "r"(a3), "r"(b0), "r"(b1));
}
__device__ __forceinline__ uint32_t ldu(const float* p) { return __float_as_uint(*p); }

// One warp computes M=16 rows (own rows) x N=128 over K=128 from smem A/B.
// A: asm[row][k] stride ES, rows mrow0..mrow0+15. B: wsm[n][k] stride ES.
__device__ __forceinline__ void warp_gemm_16x128x128(
    float acc[16][4], const float* __restrict__ asm_, const float* __restrict__ wsm,
    int mrow0, int g, int q) {
    const float* ar0 = asm_ + (mrow0 + g) * ES + q;
    const float* ar1 = ar0 + 8 * ES;
    #pragma unroll
    for (int kc = 0; kc < 16; kc++) {
        int k0 = kc * 8;
        uint32_t a0 = ldu(ar0 + k0),     a2 = ldu(ar0 + k0 + 4);
        uint32_t a1 = ldu(ar1 + k0),     a3 = ldu(ar1 + k0 + 4);
        const float* wb = wsm + g * ES + k0 + q;
        #pragma unroll
        for (int nt = 0; nt < 16; nt++) {
            uint32_t b0 = ldu(wb + nt * 8 * ES);
            uint32_t b1 = ldu(wb + nt * 8 * ES + 4);
            mma8(acc[nt], a0, a1, a2, a3, b0, b1);
        }
    }
}

// ---------------- prep: transpose off_W1 ----------------
__global__ void prep_kernel(const float* __restrict__ off_W1) {
    int i0 = blockIdx.x * blockDim.x + threadIdx.x, st = gridDim.x * blockDim.x;
    for (int x = i0; x < CC*CC; x += st) {
        int i = x >> 7, j = x & 127;
        g_offW1t[x] = off_W1[j*CC + i];
    }
}

// ---------------- offset MLP (scalar fp32, exact) ----------------
__global__ __launch_bounds__(128) void offset_kernel(
    const float* __restrict__ feat, const float* __restrict__ xyz,
    const float* __restrict__ b1, const float* __restrict__ W2,
    const float* __restrict__ b2) {
    const int P = 8;
    __shared__ __align__(16) float fs[P][CC];
    __shared__ __align__(16) float hs[P][CC];
    int tid = threadIdx.x;
    int p0 = blockIdx.x * P;

    #pragma unroll
    for (int p = 0; p < P; p++) fs[p][tid] = feat[(size_t)(p0+p)*CC + tid];
    __syncthreads();

    float acc[P];
    float bb = b1[tid];
    #pragma unroll
    for (int p = 0; p < P; p++) acc[p] = bb;

    for (int m = 0; m < CC/4; m++) {
        float w0 = g_offW1t[(4*m+0)*CC + tid];
        float w1 = g_offW1t[(4*m+1)*CC + tid];
        float w2 = g_offW1t[(4*m+2)*CC + tid];
        float w3 = g_offW1t[(4*m+3)*CC + tid];
        #pragma unroll
        for (int p = 0; p < P; p++) {
            float4 f = *(const float4*)&fs[p][4*m];
            acc[p] += w0*f.x + w1*f.y + w2*f.z + w3*f.w;
        }
    }
    #pragma unroll
    for (int p = 0; p < P; p++) hs[p][tid] = fmaxf(acc[p], 0.f);
    __syncthreads();

    if (tid < P*3) {
        int p = tid / 3, d = tid - 3*p;
        float s = b2[d];
        for (int i = 0; i < CC; i++) s += hs[p][i] * W2[d*CC + i];
        int g = p0 + p;
        g_center[g*3 + d] = xyz[g*3 + d] + s;
    }
}

// ---------------- edge kernel: persistent, warp mma.sync tf32 ----------------
// dyn smem layout (floats): es[128*ES], wb1[128*ES], wb2[128*ES],
//                           relpos f4[128], posw f4[128], eb2s[128], idxs[128]
#define EO_ES   0
#define EO_WB1  (128*ES)
#define EO_WB2  (2*128*ES)
#define EO_RP   (3*128*ES)          // float4[128] -> 512 floats
#define EO_PW   (3*128*ES + 512)
#define EO_EB2  (3*128*ES + 1024)
#define EO_IDX  (3*128*ES + 1152)
#define E_SMEMF (3*128*ES + 1280)
#define E_SMEM  (E_SMEMF*4)

__global__ void __launch_bounds__(256, 1) edge_kernel(
    const float* __restrict__ feat_src, const float* __restrict__ xyz,
    const int* __restrict__ knn,
    const float* __restrict__ eW1, const float* __restrict__ eb1,
    const float* __restrict__ eW2, const float* __restrict__ eb2,
    int t) {
    extern __shared__ __align__(16) float sm[];
    float*  es   = sm + EO_ES;
    float*  wb1  = sm + EO_WB1;
    float*  wb2  = sm + EO_WB2;
    float4* relpos = (float4*)(sm + EO_RP);
    float4* posw   = (float4*)(sm + EO_PW);
    float*  eb2s   = sm + EO_EB2;
    int*    idxs   = (int*)(sm + EO_IDX);

    const int tid = threadIdx.x, wid = tid >> 5, lid = tid & 31;
    const int g = lid >> 2, q = lid & 3;
    const int mrow0 = wid * 16;

    const float* eW1t = eW1 + (size_t)t*CC*CE;
    const float* eW2t = eW2 + (size_t)t*CC*CC;

    // fill weights once (persistent CTA)
    for (int x = tid; x < CC*CC; x += 256) {
        int n = x >> 7, k = x & 127;
        wb1[n*ES + k] = f2tf(eW1t[n*CE + 3 + k]);
        wb2[n*ES + k] = f2tf(eW2t[n*CC + k]);
    }
    if (tid < CC) {
        const float* w = eW1t + tid*CE;
        posw[tid] = make_float4(w[0], w[1], w[2], eb1[t*CC + tid]);
        eb2s[tid] = eb2[t*CC + tid];
    }
    __syncthreads();

    for (int tt = blockIdx.x; tt < NTILES; tt += gridDim.x) {
        int p0 = tt * 8;
        int base = p0 & ~(NN - 1);

        if (tid < 128) idxs[tid] = knn[(size_t)p0*KK + tid];
        __syncthreads();   // also closes previous tile's compute

        // gather neighbor feats (tf32) + rel_pos (exact fp32)
        for (int r = wid; r < 128; r += 8) {
            const float4* src = (const float4*)(feat_src + (size_t)(base + idxs[r])*CC);
            *(float4*)&es[r*ES + lid*4] = f2tf4(src[lid]);
        }
        if (tid < 128) {
            int r = tid, p = p0 + (r >> 4), nb = base + idxs[r];
            float cx = g_center[p*3+0], cy = g_center[p*3+1], cz = g_center[p*3+2];
            relpos[r] = make_float4(xyz[nb*3+0]-cx, xyz[nb*3+1]-cy, xyz[nb*3+2]-cz, 0.f);
        }
        __syncthreads();

        // ---- layer 1: feat part via mma, K=128 ----
        float acc[16][4];
        #pragma unroll
        for (int nt = 0; nt < 16; nt++)
            acc[nt][0] = acc[nt][1] = acc[nt][2] = acc[nt][3] = 0.f;
        warp_gemm_16x128x128(acc, es, wb1, mrow0, g, q);

        // epilogue1 (own rows only -> no sync needed):
        // + rel_pos·W + b1 (exact fp32), ReLU, tf32, back into es
        {
            int r0 = mrow0 + g, r1 = r0 + 8;
            float4 rp0 = relpos[r0], rp1 = relpos[r1];
            #pragma unroll
            for (int nt = 0; nt < 16; nt++) {
                int n = nt*8 + q*2;
                float4 pwa = posw[n], pwb = posw[n+1];
                float pa0 = rp0.x*pwa.x + rp0.y*pwa.y + rp0.z*pwa.z + pwa.w;
                float pb0 = rp0.x*pwb.x + rp0.y*pwb.y + rp0.z*pwb.z + pwb.w;
                float pa1 = rp1.x*pwa.x + rp1.y*pwa.y + rp1.z*pwa.z + pwa.w;
                float pb1 = rp1.x*pwb.x + rp1.y*pwb.y + rp1.z*pwb.z + pwb.w;
                float2 v0 = make_float2(f2tf(fmaxf(acc[nt][0] + pa0, 0.f)),
                                        f2tf(fmaxf(acc[nt][1] + pb0, 0.f)));
                float2 v1 = make_float2(f2tf(fmaxf(acc[nt][2] + pa1, 0.f)),
                                        f2tf(fmaxf(acc[nt][3] + pb1, 0.f)));
                *(float2*)&es[r0*ES + n] = v0;
                *(float2*)&es[r1*ES + n] = v1;
            }
        }

        // ---- layer 2 (reads own rows + wb2) ----
        #pragma unroll
        for (int nt = 0; nt < 16; nt++)
            acc[nt][0] = acc[nt][1] = acc[nt][2] = acc[nt][3] = 0.f;
        warp_gemm_16x128x128(acc, es, wb2, mrow0, g, q);

        // epilogue2: max over this warp's 16 rows (= point p0+wid), +b2 -> g_agg
        {
            int p = p0 + wid;
            float* outp = g_agg + (size_t)p*CC;
            #pragma unroll
            for (int nt = 0; nt < 16; nt++) {
                float m0 = fmaxf(acc[nt][0], acc[nt][2]);
                float m1 = fmaxf(acc[nt][1], acc[nt][3]);
                #pragma unroll
                for (int s = 4; s <= 16; s <<= 1) {
                    m0 = fmaxf(m0, __shfl_xor_sync(0xffffffffu, m0, s));
                    m1 = fmaxf(m1, __shfl_xor_sync(0xffffffffu, m1, s));
                }
                if (g == 0) {
                    int n = nt*8 + q*2;
                    *(float2*)&outp[n] = make_float2(m0 + eb2s[n], m1 + eb2s[n+1]);
                }
            }
        }
        // next-tile barrier is at loop top
    }
}

// ---------------- upd kernel: warp mma.sync tf32, 128 points/CTA ----------------
// dyn smem: au[128*ES], wbuf[128*ES], ub1s[128], ub2s[128]
#define UO_A    0
#define UO_W    (128*ES)
#define UO_B1   (2*128*ES)
#define UO_B2   (2*128*ES + 128)
#define U_SMEMF (2*128*ES + 256)
#define U_SMEM  (U_SMEMF*4)

__global__ void __launch_bounds__(256, 1) upd_kernel(
    const float* __restrict__ src, float* __restrict__ dst,
    const float* __restrict__ uW1, const float* __restrict__ uW2,
    const float* __restrict__ ub1, const float* __restrict__ ub2) {
    extern __shared__ __align__(16) float sm[];
    float* au   = sm + UO_A;
    float* wbuf = sm + UO_W;
    float* ub1s = sm + UO_B1;
    float* ub2s = sm + UO_B2;

    const int tid = threadIdx.x, wid = tid >> 5, lid = tid & 31;
    const int g = lid >> 2, q = lid & 3;
    const int mrow0 = wid * 16;
    int p0 = blockIdx.x * 128;

    // pass 1: A = agg, B = uW1[:, 0:128]
    for (int r = wid; r < 128; r += 8) {
        const float4* a = (const float4*)(g_agg + (size_t)(p0+r)*CC);
        *(float4*)&au[r*ES + lid*4] = f2tf4(a[lid]);
        const float4* w = (const float4*)(uW1 + (size_t)r*2*CC);
        *(float4*)&wbuf[r*ES + lid*4] = f2tf4(w[lid]);
    }
    if (tid < CC) { ub1s[tid] = ub1[tid]; ub2s[tid] = ub2[tid]; }
    __syncthreads();

    float acc[16][4];
    #pragma unroll
    for (int nt = 0; nt < 16; nt++)
        acc[nt][0] = acc[nt][1] = acc[nt][2] = acc[nt][3] = 0.f;
    warp_gemm_16x128x128(acc, au, wbuf, mrow0, g, q);
    __syncthreads();

    // pass 2: A = feat, B = uW1[:, 128:256]
    for (int r = wid; r < 128; r += 8) {
        const float4* a = (const float4*)(src + (size_t)(p0+r)*CC);
        *(float4*)&au[r*ES + lid*4] = f2tf4(a[lid]);
        const float4* w = (const float4*)(uW1 + (size_t)r*2*CC + CC);
        *(float4*)&wbuf[r*ES + lid*4] = f2tf4(w[lid]);
    }
    __syncthreads();
    warp_gemm_16x128x128(acc, au, wbuf, mrow0, g, q);

    // epilogue1: relu(acc + ub1) -> au own rows (safe: rows read/written only by owner warp)
    {
        int r0 = mrow0 + g, r1 = r0 + 8;
        #pragma unroll
        for (int nt = 0; nt < 16; nt++) {
            int n = nt*8 + q*2;
            float b0 = ub1s[n], b1 = ub1s[n+1];
            *(float2*)&au[r0*ES + n] = make_float2(f2tf(fmaxf(acc[nt][0] + b0, 0.f)),
                                                   f2tf(fmaxf(acc[nt][1] + b1, 0.f)));
            *(float2*)&au[r1*ES + n] = make_float2(f2tf(fmaxf(acc[nt][2] + b0, 0.f)),
                                                   f2tf(fmaxf(acc[nt][3] + b1, 0.f)));
        }
    }
    __syncthreads();   // all done reading wbuf (pass2)

    // B = uW2
    for (int r = wid; r < 128; r += 8) {
        const float4* w = (const float4*)(uW2 + (size_t)r*CC);
        *(float4*)&wbuf[r*ES + lid*4] = f2tf4(w[lid]);
    }
    __syncthreads();

    #pragma unroll
    for (int nt = 0; nt < 16; nt++)
        acc[nt][0] = acc[nt][1] = acc[nt][2] = acc[nt][3] = 0.f;
    warp_gemm_16x128x128(acc, au, wbuf, mrow0, g, q);

    // epilogue2: out = acc + ub2 + src (fp32 residual)
    {
        int r0 = mrow0 + g, r1 = r0 + 8;
        const float* s0 = src + (size_t)(p0+r0)*CC;
        const float* s1 = src + (size_t)(p0+r1)*CC;
        float* d0 = dst + (size_t)(p0+r0)*CC;
        float* d1 = dst + (size_t)(p0+r1)*CC;
        #pragma unroll
        for (int nt = 0; nt < 16; nt++) {
            int n = nt*8 + q*2;
            float b0 = ub2s[n], b1 = ub2s[n+1];
            float2 x0 = *(const float2*)&s0[n];
            float2 x1 = *(const float2*)&s1[n];
            *(float2*)&d0[n] = make_float2(acc[nt][0] + b0 + x0.x, acc[nt][1] + b1 + x0.y);
            *(float2*)&d1[n] = make_float2(acc[nt][2] + b0 + x1.x, acc[nt][3] + b1 + x1.y);
        }
    }
}

// ---------------- launch ----------------
extern "C" void kernel_launch(void* const* d_in, const int* in_sizes, int n_in,
                              void* d_out, int out_size) {
    const float* xyz      = (const float*)d_in[0];
    const float* features = (const float*)d_in[1];
    const int*   knn      = (const int*)  d_in[2];
    const float* off_W1   = (const float*)d_in[3];
    const float* off_b1   = (const float*)d_in[4];
    const float* off_W2   = (const float*)d_in[5];
    const float* off_b2   = (const float*)d_in[6];
    const float* edge_W1  = (const float*)d_in[7];
    const float* edge_b1  = (const float*)d_in[8];
    const float* edge_W2  = (const float*)d_in[9];
    const float* edge_b2  = (const float*)d_in[10];
    const float* upd_W1   = (const float*)d_in[11];
    const float* upd_b1   = (const float*)d_in[12];
    const float* upd_W2   = (const float*)d_in[13];
    const float* upd_b2   = (const float*)d_in[14];
    float* out = (float*)d_out;

    float *featA, *featB;
    cudaGetSymbolAddress((void**)&featA, g_featA);
    cudaGetSymbolAddress((void**)&featB, g_featB);

    cudaFuncSetAttribute(edge_kernel, cudaFuncAttributeMaxDynamicSharedMemorySize, E_SMEM);
    cudaFuncSetAttribute(upd_kernel,  cudaFuncAttributeMaxDynamicSharedMemorySize, U_SMEM);
    int nsm = 148;
    cudaDeviceGetAttribute(&nsm, cudaDevAttrMultiProcessorCount, 0);

    prep_kernel<<<64, 256>>>(off_W1);

    const float* src = features;
    for (int t = 0; t < TT; t++) {
        float* dst = (t == TT-1) ? out : ((t == 0) ? featA : featB);
        offset_kernel<<<BN_/8, 128>>>(src, xyz, off_b1, off_W2, off_b2);
        edge_kernel<<<nsm, 256, E_SMEM>>>(src, xyz, knn,
                                          edge_W1, edge_b1, edge_W2, edge_b2, t);
        upd_kernel<<<BN_/128, 256, U_SMEM>>>(src, dst,
                                             upd_W1 + (size_t)t*2*CC*CC, upd_W2 + (size_t)t*CC*CC,
                                             upd_b1 + t*CC, upd_b2 + t*CC);
        src = dst;
    }
}

// round 8
// speedup vs baseline: 4.4463x; 1.1688x over previous
#include <cuda_runtime.h>
#include <cuda_bf16.h>
#include <cstdint>

#define BB 4
#define NN 8192
#define KK 16
#define CC 128
#define TT 3
#define BN_ (BB*NN)          // 32768 points
#define CE 131               // 3 + C
#define NTILES (BN_/8)       // 4096 edge tiles (8 points x 16 nbrs = 128 rows)
#define ES 132               // padded A row stride (floats) -> conflict-free frags

// ---------------- device scratch ----------------
__device__ __align__(16) float g_featA[BN_*CC];
__device__ __align__(16) float g_featB[BN_*CC];
__device__ __align__(16) float g_agg[BN_*CC];
__device__ float  g_center[BN_*3];
__device__ float4 g_posw[TT*CC];        // {w0,w1,w2,b1} per edge output n
// packed tf32 weight fragments: idx y in [0,4096): lid=y&31, nt=(y>>5)&15, p2=y>>9
// float4 = {W[n][16p2+q], W[n][16p2+q+4], W[n][16p2+q+8], W[n][16p2+q+12]}, n=nt*8+(lid>>2), q=lid&3
__device__ float4 g_pkE1[TT][4096];
__device__ float4 g_pkE2[TT][4096];
__device__ float4 g_pkU1[TT][2][4096];
__device__ float4 g_pkU2[TT][4096];
__device__ float4 g_pkO1[4096];
__device__ float4 g_pkO2[256];          // n8 fragment (rows 3..7 zero): x: lid=x&31, p2=x>>5

// ---------------- helpers ----------------
__device__ __forceinline__ float f2tf(float x) {
    uint32_t u; asm("cvt.rna.tf32.f32 %0, %1;" : "=r"(u) : "f"(x));
    return __uint_as_float(u);
}
__device__ __forceinline__ float4 f2tf4(float4 v) {
    v.x = f2tf(v.x); v.y = f2tf(v.y); v.z = f2tf(v.z); v.w = f2tf(v.w);
    return v;
}
__device__ __forceinline__ void mma8(float* c, uint32_t a0, uint32_t a1,
                                     uint32_t a2, uint32_t a3,
                                     uint32_t b0, uint32_t b1) {
    asm volatile(
        "mma.sync.aligned.m16n8k8.row.col.f32.tf32.tf32.f32 "
        "{%0,%1,%2,%3}, {%4,%5,%6,%7}, {%8,%9}, {%0,%1,%2,%3};"
        : "+f"(c[0]), "+f"(c[1]), "+f"(c[2]), "+f"(c[3])
        : "r"(a0), "r"(a1), "r"(a2), "r"(a3), "r"(b0), "r"(b1));
}
__device__ __forceinline__ uint32_t ldu(const float* p) { return __float_as_uint(*p); }

// warp GEMM: 16 rows (mrow0..mrow0+15) x 128 N over K=128.
// A row-major in smem (stride ES); B packed fragments (float4/lane per kc-pair/nt).
__device__ __forceinline__ void wgemm(float acc[16][4], const float* __restrict__ abase,
                                      const float4* __restrict__ pb,
                                      int mrow0, int g, int q, int lid) {
    const float* ar0 = abase + (mrow0 + g) * ES + q;
    const float* ar1 = ar0 + 8 * ES;
    #pragma unroll
    for (int p2 = 0; p2 < 8; p2++) {
        int k0 = p2 * 16;
        uint32_t aE0 = ldu(ar0 + k0),      aE2 = ldu(ar0 + k0 + 4);
        uint32_t aE1 = ldu(ar1 + k0),      aE3 = ldu(ar1 + k0 + 4);
        uint32_t aO0 = ldu(ar0 + k0 + 8),  aO2 = ldu(ar0 + k0 + 12);
        uint32_t aO1 = ldu(ar1 + k0 + 8),  aO3 = ldu(ar1 + k0 + 12);
        const float4* pbl = pb + p2 * 512 + lid;
        #pragma unroll
        for (int nt = 0; nt < 16; nt++) {
            float4 w = pbl[nt * 32];
            mma8(acc[nt], aE0, aE1, aE2, aE3, __float_as_uint(w.x), __float_as_uint(w.y));
            mma8(acc[nt], aO0, aO1, aO2, aO3, __float_as_uint(w.z), __float_as_uint(w.w));
        }
    }
}

// ---------------- prep: pack all weights into tf32 fragment layout ----------------
__global__ void prep_kernel(const float* __restrict__ off_W1, const float* __restrict__ off_W2,
                            const float* __restrict__ edge_W1, const float* __restrict__ edge_b1,
                            const float* __restrict__ edge_W2,
                            const float* __restrict__ upd_W1, const float* __restrict__ upd_W2) {
    int i0 = blockIdx.x * blockDim.x + threadIdx.x, st = gridDim.x * blockDim.x;
    for (int x = i0; x < TT * 4096; x += st) {
        int t = x >> 12, y = x & 4095;
        int lid = y & 31, nt = (y >> 5) & 15, p2 = y >> 9;
        int n = nt * 8 + (lid >> 2), q = lid & 3, k = p2 * 16 + q;
        const float* s1 = edge_W1 + ((size_t)t * CC + n) * CE + 3;
        g_pkE1[t][y] = make_float4(f2tf(s1[k]), f2tf(s1[k+4]), f2tf(s1[k+8]), f2tf(s1[k+12]));
        const float* s2 = edge_W2 + ((size_t)t * CC + n) * CC;
        g_pkE2[t][y] = make_float4(f2tf(s2[k]), f2tf(s2[k+4]), f2tf(s2[k+8]), f2tf(s2[k+12]));
        const float* u1 = upd_W1 + ((size_t)t * CC + n) * 2 * CC;
        g_pkU1[t][0][y] = make_float4(f2tf(u1[k]), f2tf(u1[k+4]), f2tf(u1[k+8]), f2tf(u1[k+12]));
        const float* u1b = u1 + CC;
        g_pkU1[t][1][y] = make_float4(f2tf(u1b[k]), f2tf(u1b[k+4]), f2tf(u1b[k+8]), f2tf(u1b[k+12]));
        const float* u2 = upd_W2 + ((size_t)t * CC + n) * CC;
        g_pkU2[t][y] = make_float4(f2tf(u2[k]), f2tf(u2[k+4]), f2tf(u2[k+8]), f2tf(u2[k+12]));
    }
    for (int x = i0; x < 4096; x += st) {
        int lid = x & 31, nt = (x >> 5) & 15, p2 = x >> 9;
        int n = nt * 8 + (lid >> 2), q = lid & 3, k = p2 * 16 + q;
        const float* s = off_W1 + (size_t)n * CC;
        g_pkO1[x] = make_float4(f2tf(s[k]), f2tf(s[k+4]), f2tf(s[k+8]), f2tf(s[k+12]));
    }
    for (int x = i0; x < 256; x += st) {
        int lid = x & 31, p2 = x >> 5;
        int n = lid >> 2, q = lid & 3, k = p2 * 16 + q;
        if (n < 3) {
            const float* s = off_W2 + (size_t)n * CC;
            g_pkO2[x] = make_float4(f2tf(s[k]), f2tf(s[k+4]), f2tf(s[k+8]), f2tf(s[k+12]));
        } else {
            g_pkO2[x] = make_float4(0.f, 0.f, 0.f, 0.f);
        }
    }
    for (int x = i0; x < TT * CC; x += st) {
        int t = x >> 7, n = x & 127;
        const float* w = edge_W1 + ((size_t)t * CC + n) * CE;
        g_posw[x] = make_float4(w[0], w[1], w[2], edge_b1[t * CC + n]);
    }
}

// ---------------- offset kernel: tensor-core, 256 points/CTA ----------------
// smem floats: fs[256*ES]=33792, pkO1=16384 (f4 4096), pkO2=1024 (f4 256), b1[128], b2[4]
#define OO_F    0
#define OO_W1   33792
#define OO_W2   50176
#define OO_B1   51200
#define OO_B2   51328
#define O_SMEMF 51336
#define O_SMEM  (O_SMEMF*4)

__global__ void __launch_bounds__(512) offset_kernel(
    const float* __restrict__ feat, const float* __restrict__ xyz,
    const float* __restrict__ b1, const float* __restrict__ b2) {
    extern __shared__ __align__(16) float sm[];
    float*  fs  = sm + OO_F;
    float4* w1s = (float4*)(sm + OO_W1);
    float4* w2s = (float4*)(sm + OO_W2);
    float*  b1s = sm + OO_B1;
    float*  b2s = sm + OO_B2;

    const int tid = threadIdx.x, wid = tid >> 5, lid = tid & 31;
    const int g = lid >> 2, q = lid & 3;
    const int mrow0 = wid * 16;
    int p0 = blockIdx.x * 256;

    for (int i = tid; i < 4096; i += 512) w1s[i] = g_pkO1[i];
    if (tid < 256) w2s[tid] = g_pkO2[tid];
    if (tid < CC) b1s[tid] = b1[tid];
    if (tid < 3) b2s[tid] = b2[tid];
    for (int r = wid; r < 256; r += 16) {
        const float4* src = (const float4*)(feat + (size_t)(p0 + r) * CC);
        *(float4*)&fs[r * ES + lid * 4] = f2tf4(src[lid]);
    }
    __syncthreads();

    // layer 1
    float acc[16][4];
    #pragma unroll
    for (int nt = 0; nt < 16; nt++)
        acc[nt][0] = acc[nt][1] = acc[nt][2] = acc[nt][3] = 0.f;
    wgemm(acc, fs, w1s, mrow0, g, q, lid);

    // epilogue: relu(+b1) -> own rows (warp-private, no sync needed)
    {
        int r0 = mrow0 + g, r1 = r0 + 8;
        #pragma unroll
        for (int nt = 0; nt < 16; nt++) {
            int n = nt * 8 + q * 2;
            float c0 = b1s[n], c1 = b1s[n + 1];
            *(float2*)&fs[r0 * ES + n] = make_float2(f2tf(fmaxf(acc[nt][0] + c0, 0.f)),
                                                     f2tf(fmaxf(acc[nt][1] + c1, 0.f)));
            *(float2*)&fs[r1 * ES + n] = make_float2(f2tf(fmaxf(acc[nt][2] + c0, 0.f)),
                                                     f2tf(fmaxf(acc[nt][3] + c1, 0.f)));
        }
    }

    // layer 2: N=3 (one zero-padded n8 fragment)
    float a2[4] = {0.f, 0.f, 0.f, 0.f};
    {
        const float* ar0 = fs + (mrow0 + g) * ES + q;
        const float* ar1 = ar0 + 8 * ES;
        #pragma unroll
        for (int p2 = 0; p2 < 8; p2++) {
            int k0 = p2 * 16;
            uint32_t aE0 = ldu(ar0 + k0),     aE2 = ldu(ar0 + k0 + 4);
            uint32_t aE1 = ldu(ar1 + k0),     aE3 = ldu(ar1 + k0 + 4);
            uint32_t aO0 = ldu(ar0 + k0 + 8), aO2 = ldu(ar0 + k0 + 12);
            uint32_t aO1 = ldu(ar1 + k0 + 8), aO3 = ldu(ar1 + k0 + 12);
            float4 w = w2s[p2 * 32 + lid];
            mma8(a2, aE0, aE1, aE2, aE3, __float_as_uint(w.x), __float_as_uint(w.y));
            mma8(a2, aO0, aO1, aO2, aO3, __float_as_uint(w.z), __float_as_uint(w.w));
        }
    }
    // cols 2q,2q+1: valid only 0..2
    {
        int r0 = p0 + mrow0 + g, r1 = r0 + 8;
        if (q == 0) {
            g_center[r0*3 + 0] = xyz[r0*3 + 0] + a2[0] + b2s[0];
            g_center[r0*3 + 1] = xyz[r0*3 + 1] + a2[1] + b2s[1];
            g_center[r1*3 + 0] = xyz[r1*3 + 0] + a2[2] + b2s[0];
            g_center[r1*3 + 1] = xyz[r1*3 + 1] + a2[3] + b2s[1];
        } else if (q == 1) {
            g_center[r0*3 + 2] = xyz[r0*3 + 2] + a2[0] + b2s[2];
            g_center[r1*3 + 2] = xyz[r1*3 + 2] + a2[2] + b2s[2];
        }
    }
}

// ---------------- edge kernel: persistent, packed-B warp mma ----------------
// smem floats: es[128*ES]=16896, w1 f4[4096]=16384, w2 f4[4096]=16384,
//              relpos f4[128]=512, posw f4[128]=512, eb2[128], idx[128]
#define EO_ES   0
#define EO_W1   16896
#define EO_W2   33280
#define EO_RP   49664
#define EO_PW   50176
#define EO_EB2  50688
#define EO_IDX  50816
#define E_SMEMF 50944
#define E_SMEM  (E_SMEMF*4)

__global__ void __launch_bounds__(256, 1) edge_kernel(
    const float* __restrict__ feat_src, const float* __restrict__ xyz,
    const int* __restrict__ knn, const float* __restrict__ eb2, int t) {
    extern __shared__ __align__(16) float sm[];
    float*  es   = sm + EO_ES;
    float4* w1s  = (float4*)(sm + EO_W1);
    float4* w2s  = (float4*)(sm + EO_W2);
    float4* relpos = (float4*)(sm + EO_RP);
    float4* posw   = (float4*)(sm + EO_PW);
    float*  eb2s   = sm + EO_EB2;
    int*    idxs   = (int*)(sm + EO_IDX);

    const int tid = threadIdx.x, wid = tid >> 5, lid = tid & 31;
    const int g = lid >> 2, q = lid & 3;
    const int mrow0 = wid * 16;

    for (int i = tid; i < 4096; i += 256) { w1s[i] = g_pkE1[t][i]; w2s[i] = g_pkE2[t][i]; }
    if (tid < CC) { posw[tid] = g_posw[t * CC + tid]; eb2s[tid] = eb2[t * CC + tid]; }
    __syncthreads();

    for (int tt = blockIdx.x; tt < NTILES; tt += gridDim.x) {
        int p0 = tt * 8;
        int base = p0 & ~(NN - 1);

        if (tid < 128) idxs[tid] = knn[(size_t)p0 * KK + tid];
        __syncthreads();   // also closes previous tile's compute

        for (int r = wid; r < 128; r += 8) {
            const float4* src = (const float4*)(feat_src + (size_t)(base + idxs[r]) * CC);
            *(float4*)&es[r * ES + lid * 4] = f2tf4(src[lid]);
        }
        if (tid < 128) {
            int r = tid, p = p0 + (r >> 4), nb = base + idxs[r];
            float cx = g_center[p*3+0], cy = g_center[p*3+1], cz = g_center[p*3+2];
            relpos[r] = make_float4(xyz[nb*3+0]-cx, xyz[nb*3+1]-cy, xyz[nb*3+2]-cz, 0.f);
        }
        __syncthreads();

        // layer 1 (feat part)
        float acc[16][4];
        #pragma unroll
        for (int nt = 0; nt < 16; nt++)
            acc[nt][0] = acc[nt][1] = acc[nt][2] = acc[nt][3] = 0.f;
        wgemm(acc, es, w1s, mrow0, g, q, lid);

        // epilogue1: + rel_pos·W + b1 (exact fp32), ReLU, tf32 -> own rows
        {
            int r0 = mrow0 + g, r1 = r0 + 8;
            float4 rp0 = relpos[r0], rp1 = relpos[r1];
            #pragma unroll
            for (int nt = 0; nt < 16; nt++) {
                int n = nt * 8 + q * 2;
                float4 pwa = posw[n], pwb = posw[n + 1];
                float pa0 = rp0.x*pwa.x + rp0.y*pwa.y + rp0.z*pwa.z + pwa.w;
                float pb0 = rp0.x*pwb.x + rp0.y*pwb.y + rp0.z*pwb.z + pwb.w;
                float pa1 = rp1.x*pwa.x + rp1.y*pwa.y + rp1.z*pwa.z + pwa.w;
                float pb1 = rp1.x*pwb.x + rp1.y*pwb.y + rp1.z*pwb.z + pwb.w;
                *(float2*)&es[r0 * ES + n] = make_float2(f2tf(fmaxf(acc[nt][0] + pa0, 0.f)),
                                                         f2tf(fmaxf(acc[nt][1] + pb0, 0.f)));
                *(float2*)&es[r1 * ES + n] = make_float2(f2tf(fmaxf(acc[nt][2] + pa1, 0.f)),
                                                         f2tf(fmaxf(acc[nt][3] + pb1, 0.f)));
            }
        }

        // layer 2 (own rows)
        #pragma unroll
        for (int nt = 0; nt < 16; nt++)
            acc[nt][0] = acc[nt][1] = acc[nt][2] = acc[nt][3] = 0.f;
        wgemm(acc, es, w2s, mrow0, g, q, lid);

        // epilogue2: max over this warp's 16 rows (= point p0+wid), +b2 -> g_agg
        {
            int p = p0 + wid;
            float* outp = g_agg + (size_t)p * CC;
            #pragma unroll
            for (int nt = 0; nt < 16; nt++) {
                float m0 = fmaxf(acc[nt][0], acc[nt][2]);
                float m1 = fmaxf(acc[nt][1], acc[nt][3]);
                #pragma unroll
                for (int s = 4; s <= 16; s <<= 1) {
                    m0 = fmaxf(m0, __shfl_xor_sync(0xffffffffu, m0, s));
                    m1 = fmaxf(m1, __shfl_xor_sync(0xffffffffu, m1, s));
                }
                if (g == 0) {
                    int n = nt * 8 + q * 2;
                    *(float2*)&outp[n] = make_float2(m0 + eb2s[n], m1 + eb2s[n + 1]);
                }
            }
        }
    }
}

// ---------------- upd kernel: 512 threads, 256 points/CTA ----------------
// smem floats: au[256*ES]=33792, wbuf f4[4096]=16384, ub1[128], ub2[128]
#define UO_A    0
#define UO_W    33792
#define UO_B1   50176
#define UO_B2   50304
#define U_SMEMF 50432
#define U_SMEM  (U_SMEMF*4)

__global__ void __launch_bounds__(512) upd_kernel(
    const float* __restrict__ src, float* __restrict__ dst,
    const float* __restrict__ ub1, const float* __restrict__ ub2, int t) {
    extern __shared__ __align__(16) float sm[];
    float*  au   = sm + UO_A;
    float4* wbuf = (float4*)(sm + UO_W);
    float*  ub1s = sm + UO_B1;
    float*  ub2s = sm + UO_B2;

    const int tid = threadIdx.x, wid = tid >> 5, lid = tid & 31;
    const int g = lid >> 2, q = lid & 3;
    const int mrow0 = wid * 16;
    int p0 = blockIdx.x * 256;

    // pass 1: A = agg, B = uW1[:, 0:128]
    for (int r = wid; r < 256; r += 16) {
        const float4* a = (const float4*)(g_agg + (size_t)(p0 + r) * CC);
        *(float4*)&au[r * ES + lid * 4] = f2tf4(a[lid]);
    }
    for (int i = tid; i < 4096; i += 512) wbuf[i] = g_pkU1[t][0][i];
    if (tid < CC) { ub1s[tid] = ub1[t*CC + tid]; ub2s[tid] = ub2[t*CC + tid]; }
    __syncthreads();

    float acc[16][4];
    #pragma unroll
    for (int nt = 0; nt < 16; nt++)
        acc[nt][0] = acc[nt][1] = acc[nt][2] = acc[nt][3] = 0.f;
    wgemm(acc, au, wbuf, mrow0, g, q, lid);
    __syncthreads();

    // pass 2: A = feat, B = uW1[:, 128:256], accumulate
    for (int r = wid; r < 256; r += 16) {
        const float4* a = (const float4*)(src + (size_t)(p0 + r) * CC);
        *(float4*)&au[r * ES + lid * 4] = f2tf4(a[lid]);
    }
    for (int i = tid; i < 4096; i += 512) wbuf[i] = g_pkU1[t][1][i];
    __syncthreads();
    wgemm(acc, au, wbuf, mrow0, g, q, lid);

    // epilogue1: relu(acc + ub1) -> own rows
    {
        int r0 = mrow0 + g, r1 = r0 + 8;
        #pragma unroll
        for (int nt = 0; nt < 16; nt++) {
            int n = nt * 8 + q * 2;
            float b0 = ub1s[n], b1 = ub1s[n + 1];
            *(float2*)&au[r0 * ES + n] = make_float2(f2tf(fmaxf(acc[nt][0] + b0, 0.f)),
                                                     f2tf(fmaxf(acc[nt][1] + b1, 0.f)));
            *(float2*)&au[r1 * ES + n] = make_float2(f2tf(fmaxf(acc[nt][2] + b0, 0.f)),
                                                     f2tf(fmaxf(acc[nt][3] + b1, 0.f)));
        }
    }
    __syncthreads();   // all warps done reading wbuf (pass2)

    for (int i = tid; i < 4096; i += 512) wbuf[i] = g_pkU2[t][i];
    __syncthreads();

    #pragma unroll
    for (int nt = 0; nt < 16; nt++)
        acc[nt][0] = acc[nt][1] = acc[nt][2] = acc[nt][3] = 0.f;
    wgemm(acc, au, wbuf, mrow0, g, q, lid);

    // epilogue2: out = acc + ub2 + src (fp32 residual)
    {
        int r0 = mrow0 + g, r1 = r0 + 8;
        const float* s0 = src + (size_t)(p0 + r0) * CC;
        const float* s1 = src + (size_t)(p0 + r1) * CC;
        float* d0 = dst + (size_t)(p0 + r0) * CC;
        float* d1 = dst + (size_t)(p0 + r1) * CC;
        #pragma unroll
        for (int nt = 0; nt < 16; nt++) {
            int n = nt * 8 + q * 2;
            float b0 = ub2s[n], b1 = ub2s[n + 1];
            float2 x0 = *(const float2*)&s0[n];
            float2 x1 = *(const float2*)&s1[n];
            *(float2*)&d0[n] = make_float2(acc[nt][0] + b0 + x0.x, acc[nt][1] + b1 + x0.y);
            *(float2*)&d1[n] = make_float2(acc[nt][2] + b0 + x1.x, acc[nt][3] + b1 + x1.y);
        }
    }
}

// ---------------- launch ----------------
extern "C" void kernel_launch(void* const* d_in, const int* in_sizes, int n_in,
                              void* d_out, int out_size) {
    const float* xyz      = (const float*)d_in[0];
    const float* features = (const float*)d_in[1];
    const int*   knn      = (const int*)  d_in[2];
    const float* off_W1   = (const float*)d_in[3];
    const float* off_b1   = (const float*)d_in[4];
    const float* off_W2   = (const float*)d_in[5];
    const float* off_b2   = (const float*)d_in[6];
    const float* edge_W1  = (const float*)d_in[7];
    const float* edge_b1  = (const float*)d_in[8];
    const float* edge_W2  = (const float*)d_in[9];
    const float* edge_b2  = (const float*)d_in[10];
    const float* upd_W1   = (const float*)d_in[11];
    const float* upd_b1   = (const float*)d_in[12];
    const float* upd_W2   = (const float*)d_in[13];
    const float* upd_b2   = (const float*)d_in[14];
    float* out = (float*)d_out;

    float *featA, *featB;
    cudaGetSymbolAddress((void**)&featA, g_featA);
    cudaGetSymbolAddress((void**)&featB, g_featB);

    cudaFuncSetAttribute(offset_kernel, cudaFuncAttributeMaxDynamicSharedMemorySize, O_SMEM);
    cudaFuncSetAttribute(edge_kernel,   cudaFuncAttributeMaxDynamicSharedMemorySize, E_SMEM);
    cudaFuncSetAttribute(upd_kernel,    cudaFuncAttributeMaxDynamicSharedMemorySize, U_SMEM);
    int nsm = 148;
    cudaDeviceGetAttribute(&nsm, cudaDevAttrMultiProcessorCount, 0);

    prep_kernel<<<128, 256>>>(off_W1, off_W2, edge_W1, edge_b1, edge_W2, upd_W1, upd_W2);

    const float* src = features;
    for (int t = 0; t < TT; t++) {
        float* dst = (t == TT-1) ? out : ((t == 0) ? featA : featB);
        offset_kernel<<<BN_/256, 512, O_SMEM>>>(src, xyz, off_b1, off_b2);
        edge_kernel<<<nsm, 256, E_SMEM>>>(src, xyz, knn, edge_b2, t);
        upd_kernel<<<BN_/256, 512, U_SMEM>>>(src, dst, upd_b1, upd_b2, t);
        src = dst;
    }
}

// round 9
// speedup vs baseline: 4.8688x; 1.0950x over previous
#include <cuda_runtime.h>
#include <cuda_bf16.h>
#include <cstdint>

#define BB 4
#define NN 8192
#define KK 16
#define CC 128
#define TT 3
#define BN_ (BB*NN)          // 32768 points
#define CE 131               // 3 + C
#define NTILES (BN_/8)       // 4096 edge tiles (8 points x 16 nbrs = 128 rows)
#define ES 132               // padded A row stride (floats) -> conflict-free frags

// ---------------- device scratch ----------------
__device__ __align__(16) float g_featA[BN_*CC];
__device__ __align__(16) float g_featB[BN_*CC];
__device__ __align__(16) float g_agg[BN_*CC];
__device__ float  g_center[BN_*3];
__device__ float4 g_posw[TT*CC];        // {w0,w1,w2,b1} per edge output n
// packed tf32 weight fragments: idx y in [0,4096): lid=y&31, nt=(y>>5)&15, p2=y>>9
// float4 = {W[n][16p2+q], W[n][16p2+q+4], W[n][16p2+q+8], W[n][16p2+q+12]}, n=nt*8+(lid>>2), q=lid&3
__device__ float4 g_pkE1[TT][4096];
__device__ float4 g_pkE2[TT][4096];
__device__ float4 g_pkU1[TT][2][4096];
__device__ float4 g_pkU2[TT][4096];
__device__ float4 g_pkO1[4096];
__device__ float4 g_pkO2[256];          // n8 fragment (rows 3..7 zero): x: lid=x&31, p2=x>>5

// ---------------- helpers ----------------
__device__ __forceinline__ float f2tf(float x) {
    uint32_t u; asm("cvt.rna.tf32.f32 %0, %1;" : "=r"(u) : "f"(x));
    return __uint_as_float(u);
}
__device__ __forceinline__ float4 f2tf4(float4 v) {
    v.x = f2tf(v.x); v.y = f2tf(v.y); v.z = f2tf(v.z); v.w = f2tf(v.w);
    return v;
}
__device__ __forceinline__ void mma8(float* c, uint32_t a0, uint32_t a1,
                                     uint32_t a2, uint32_t a3,
                                     uint32_t b0, uint32_t b1) {
    asm volatile(
        "mma.sync.aligned.m16n8k8.row.col.f32.tf32.tf32.f32 "
        "{%0,%1,%2,%3}, {%4,%5,%6,%7}, {%8,%9}, {%0,%1,%2,%3};"
        : "+f"(c[0]), "+f"(c[1]), "+f"(c[2]), "+f"(c[3])
        : "r"(a0), "r"(a1), "r"(a2), "r"(a3), "r"(b0), "r"(b1));
}
__device__ __forceinline__ uint32_t ldu(const float* p) { return __float_as_uint(*p); }

// full warp GEMM: 16 rows x 128 N over K=128 (used by offset/upd).
__device__ __forceinline__ void wgemm(float acc[16][4], const float* __restrict__ abase,
                                      const float4* __restrict__ pb,
                                      int mrow0, int g, int q, int lid) {
    const float* ar0 = abase + (mrow0 + g) * ES + q;
    const float* ar1 = ar0 + 8 * ES;
    #pragma unroll
    for (int p2 = 0; p2 < 8; p2++) {
        int k0 = p2 * 16;
        uint32_t aE0 = ldu(ar0 + k0),      aE2 = ldu(ar0 + k0 + 4);
        uint32_t aE1 = ldu(ar1 + k0),      aE3 = ldu(ar1 + k0 + 4);
        uint32_t aO0 = ldu(ar0 + k0 + 8),  aO2 = ldu(ar0 + k0 + 12);
        uint32_t aO1 = ldu(ar1 + k0 + 8),  aO3 = ldu(ar1 + k0 + 12);
        const float4* pbl = pb + p2 * 512 + lid;
        #pragma unroll
        for (int nt = 0; nt < 16; nt++) {
            float4 w = pbl[nt * 32];
            mma8(acc[nt], aE0, aE1, aE2, aE3, __float_as_uint(w.x), __float_as_uint(w.y));
            mma8(acc[nt], aO0, aO1, aO2, aO3, __float_as_uint(w.z), __float_as_uint(w.w));
        }
    }
}

// half warp GEMM: 16 rows x 64 N (N-half `half`) over K=128 (edge kernel, 16 warps).
__device__ __forceinline__ void wgemm_h(float acc[8][4], const float* __restrict__ abase,
                                        const float4* __restrict__ pb,
                                        int mrow0, int g, int q, int lid, int half) {
    const float* ar0 = abase + (mrow0 + g) * ES + q;
    const float* ar1 = ar0 + 8 * ES;
    #pragma unroll
    for (int p2 = 0; p2 < 8; p2++) {
        int k0 = p2 * 16;
        uint32_t aE0 = ldu(ar0 + k0),      aE2 = ldu(ar0 + k0 + 4);
        uint32_t aE1 = ldu(ar1 + k0),      aE3 = ldu(ar1 + k0 + 4);
        uint32_t aO0 = ldu(ar0 + k0 + 8),  aO2 = ldu(ar0 + k0 + 12);
        uint32_t aO1 = ldu(ar1 + k0 + 8),  aO3 = ldu(ar1 + k0 + 12);
        const float4* pbl = pb + p2 * 512 + half * 256 + lid;
        #pragma unroll
        for (int ntl = 0; ntl < 8; ntl++) {
            float4 w = pbl[ntl * 32];
            mma8(acc[ntl], aE0, aE1, aE2, aE3, __float_as_uint(w.x), __float_as_uint(w.y));
            mma8(acc[ntl], aO0, aO1, aO2, aO3, __float_as_uint(w.z), __float_as_uint(w.w));
        }
    }
}

// ---------------- prep: pack all weights into tf32 fragment layout ----------------
__global__ void prep_kernel(const float* __restrict__ off_W1, const float* __restrict__ off_W2,
                            const float* __restrict__ edge_W1, const float* __restrict__ edge_b1,
                            const float* __restrict__ edge_W2,
                            const float* __restrict__ upd_W1, const float* __restrict__ upd_W2) {
    int i0 = blockIdx.x * blockDim.x + threadIdx.x, st = gridDim.x * blockDim.x;
    for (int x = i0; x < TT * 4096; x += st) {
        int t = x >> 12, y = x & 4095;
        int lid = y & 31, nt = (y >> 5) & 15, p2 = y >> 9;
        int n = nt * 8 + (lid >> 2), q = lid & 3, k = p2 * 16 + q;
        const float* s1 = edge_W1 + ((size_t)t * CC + n) * CE + 3;
        g_pkE1[t][y] = make_float4(f2tf(s1[k]), f2tf(s1[k+4]), f2tf(s1[k+8]), f2tf(s1[k+12]));
        const float* s2 = edge_W2 + ((size_t)t * CC + n) * CC;
        g_pkE2[t][y] = make_float4(f2tf(s2[k]), f2tf(s2[k+4]), f2tf(s2[k+8]), f2tf(s2[k+12]));
        const float* u1 = upd_W1 + ((size_t)t * CC + n) * 2 * CC;
        g_pkU1[t][0][y] = make_float4(f2tf(u1[k]), f2tf(u1[k+4]), f2tf(u1[k+8]), f2tf(u1[k+12]));
        const float* u1b = u1 + CC;
        g_pkU1[t][1][y] = make_float4(f2tf(u1b[k]), f2tf(u1b[k+4]), f2tf(u1b[k+8]), f2tf(u1b[k+12]));
        const float* u2 = upd_W2 + ((size_t)t * CC + n) * CC;
        g_pkU2[t][y] = make_float4(f2tf(u2[k]), f2tf(u2[k+4]), f2tf(u2[k+8]), f2tf(u2[k+12]));
    }
    for (int x = i0; x < 4096; x += st) {
        int lid = x & 31, nt = (x >> 5) & 15, p2 = x >> 9;
        int n = nt * 8 + (lid >> 2), q = lid & 3, k = p2 * 16 + q;
        const float* s = off_W1 + (size_t)n * CC;
        g_pkO1[x] = make_float4(f2tf(s[k]), f2tf(s[k+4]), f2tf(s[k+8]), f2tf(s[k+12]));
    }
    for (int x = i0; x < 256; x += st) {
        int lid = x & 31, p2 = x >> 5;
        int n = lid >> 2, q = lid & 3, k = p2 * 16 + q;
        if (n < 3) {
            const float* s = off_W2 + (size_t)n * CC;
            g_pkO2[x] = make_float4(f2tf(s[k]), f2tf(s[k+4]), f2tf(s[k+8]), f2tf(s[k+12]));
        } else {
            g_pkO2[x] = make_float4(0.f, 0.f, 0.f, 0.f);
        }
    }
    for (int x = i0; x < TT * CC; x += st) {
        int t = x >> 7, n = x & 127;
        const float* w = edge_W1 + ((size_t)t * CC + n) * CE;
        g_posw[x] = make_float4(w[0], w[1], w[2], edge_b1[t * CC + n]);
    }
}

// ---------------- offset kernel: tensor-core, 256 points/CTA ----------------
#define OO_F    0
#define OO_W1   33792
#define OO_W2   50176
#define OO_B1   51200
#define OO_B2   51328
#define O_SMEMF 51336
#define O_SMEM  (O_SMEMF*4)

__global__ void __launch_bounds__(512) offset_kernel(
    const float* __restrict__ feat, const float* __restrict__ xyz,
    const float* __restrict__ b1, const float* __restrict__ b2) {
    extern __shared__ __align__(16) float sm[];
    float*  fs  = sm + OO_F;
    float4* w1s = (float4*)(sm + OO_W1);
    float4* w2s = (float4*)(sm + OO_W2);
    float*  b1s = sm + OO_B1;
    float*  b2s = sm + OO_B2;

    const int tid = threadIdx.x, wid = tid >> 5, lid = tid & 31;
    const int g = lid >> 2, q = lid & 3;
    const int mrow0 = wid * 16;
    int p0 = blockIdx.x * 256;

    for (int i = tid; i < 4096; i += 512) w1s[i] = g_pkO1[i];
    if (tid < 256) w2s[tid] = g_pkO2[tid];
    if (tid < CC) b1s[tid] = b1[tid];
    if (tid < 3) b2s[tid] = b2[tid];
    for (int r = wid; r < 256; r += 16) {
        const float4* src = (const float4*)(feat + (size_t)(p0 + r) * CC);
        *(float4*)&fs[r * ES + lid * 4] = f2tf4(src[lid]);
    }
    __syncthreads();

    float acc[16][4];
    #pragma unroll
    for (int nt = 0; nt < 16; nt++)
        acc[nt][0] = acc[nt][1] = acc[nt][2] = acc[nt][3] = 0.f;
    wgemm(acc, fs, w1s, mrow0, g, q, lid);

    {
        int r0 = mrow0 + g, r1 = r0 + 8;
        #pragma unroll
        for (int nt = 0; nt < 16; nt++) {
            int n = nt * 8 + q * 2;
            float c0 = b1s[n], c1 = b1s[n + 1];
            *(float2*)&fs[r0 * ES + n] = make_float2(f2tf(fmaxf(acc[nt][0] + c0, 0.f)),
                                                     f2tf(fmaxf(acc[nt][1] + c1, 0.f)));
            *(float2*)&fs[r1 * ES + n] = make_float2(f2tf(fmaxf(acc[nt][2] + c0, 0.f)),
                                                     f2tf(fmaxf(acc[nt][3] + c1, 0.f)));
        }
    }

    float a2[4] = {0.f, 0.f, 0.f, 0.f};
    {
        const float* ar0 = fs + (mrow0 + g) * ES + q;
        const float* ar1 = ar0 + 8 * ES;
        #pragma unroll
        for (int p2 = 0; p2 < 8; p2++) {
            int k0 = p2 * 16;
            uint32_t aE0 = ldu(ar0 + k0),     aE2 = ldu(ar0 + k0 + 4);
            uint32_t aE1 = ldu(ar1 + k0),     aE3 = ldu(ar1 + k0 + 4);
            uint32_t aO0 = ldu(ar0 + k0 + 8), aO2 = ldu(ar0 + k0 + 12);
            uint32_t aO1 = ldu(ar1 + k0 + 8), aO3 = ldu(ar1 + k0 + 12);
            float4 w = w2s[p2 * 32 + lid];
            mma8(a2, aE0, aE1, aE2, aE3, __float_as_uint(w.x), __float_as_uint(w.y));
            mma8(a2, aO0, aO1, aO2, aO3, __float_as_uint(w.z), __float_as_uint(w.w));
        }
    }
    {
        int r0 = p0 + mrow0 + g, r1 = r0 + 8;
        if (q == 0) {
            g_center[r0*3 + 0] = xyz[r0*3 + 0] + a2[0] + b2s[0];
            g_center[r0*3 + 1] = xyz[r0*3 + 1] + a2[1] + b2s[1];
            g_center[r1*3 + 0] = xyz[r1*3 + 0] + a2[2] + b2s[0];
            g_center[r1*3 + 1] = xyz[r1*3 + 1] + a2[3] + b2s[1];
        } else if (q == 1) {
            g_center[r0*3 + 2] = xyz[r0*3 + 2] + a2[0] + b2s[2];
            g_center[r1*3 + 2] = xyz[r1*3 + 2] + a2[2] + b2s[2];
        }
    }
}

// ---------------- edge kernel: persistent, 512 threads, N-split warp mma ----------------
// smem floats: es[128*ES]=16896, w1 f4[4096]=16384, w2 f4[4096]=16384,
//              relpos f4[128]=512, posw f4[128]=512, eb2[128], idx[128]
#define EO_ES   0
#define EO_W1   16896
#define EO_W2   33280
#define EO_RP   49664
#define EO_PW   50176
#define EO_EB2  50688
#define EO_IDX  50816
#define E_SMEMF 50944
#define E_SMEM  (E_SMEMF*4)

__global__ void __launch_bounds__(512, 1) edge_kernel(
    const float* __restrict__ feat_src, const float* __restrict__ xyz,
    const int* __restrict__ knn, const float* __restrict__ eb2, int t) {
    extern __shared__ __align__(16) float sm[];
    float*  es   = sm + EO_ES;
    float4* w1s  = (float4*)(sm + EO_W1);
    float4* w2s  = (float4*)(sm + EO_W2);
    float4* relpos = (float4*)(sm + EO_RP);
    float4* posw   = (float4*)(sm + EO_PW);
    float*  eb2s   = sm + EO_EB2;
    int*    idxs   = (int*)(sm + EO_IDX);

    const int tid = threadIdx.x, wid = tid >> 5, lid = tid & 31;
    const int g = lid >> 2, q = lid & 3;
    const int rw = wid & 7;          // row group (= point within tile)
    const int hw = wid >> 3;         // N-half
    const int mrow0 = rw * 16;

    for (int i = tid; i < 4096; i += 512) { w1s[i] = g_pkE1[t][i]; w2s[i] = g_pkE2[t][i]; }
    if (tid < CC) { posw[tid] = g_posw[t * CC + tid]; eb2s[tid] = eb2[t * CC + tid]; }
    __syncthreads();

    for (int tt = blockIdx.x; tt < NTILES; tt += gridDim.x) {
        int p0 = tt * 8;
        int base = p0 & ~(NN - 1);

        if (tid < 128) idxs[tid] = knn[(size_t)p0 * KK + tid];
        __syncthreads();   // also closes previous tile's compute

        // gather: 16 warps, 8 rows each
        for (int r = wid; r < 128; r += 16) {
            const float4* src = (const float4*)(feat_src + (size_t)(base + idxs[r]) * CC);
            *(float4*)&es[r * ES + lid * 4] = f2tf4(src[lid]);
        }
        if (tid < 128) {
            int r = tid, p = p0 + (r >> 4), nb = base + idxs[r];
            float cx = g_center[p*3+0], cy = g_center[p*3+1], cz = g_center[p*3+2];
            relpos[r] = make_float4(xyz[nb*3+0]-cx, xyz[nb*3+1]-cy, xyz[nb*3+2]-cz, 0.f);
        }
        __syncthreads();

        // layer 1 (feat part) — this warp: rows of point rw, N-half hw
        float acc[8][4];
        #pragma unroll
        for (int ntl = 0; ntl < 8; ntl++)
            acc[ntl][0] = acc[ntl][1] = acc[ntl][2] = acc[ntl][3] = 0.f;
        wgemm_h(acc, es, w1s, mrow0, g, q, lid, hw);

        // epilogue1: + rel_pos·W + b1 (exact fp32), ReLU, tf32 -> own rows, own N-half
        {
            int r0 = mrow0 + g, r1 = r0 + 8;
            float4 rp0 = relpos[r0], rp1 = relpos[r1];
            #pragma unroll
            for (int ntl = 0; ntl < 8; ntl++) {
                int n = hw * 64 + ntl * 8 + q * 2;
                float4 pwa = posw[n], pwb = posw[n + 1];
                float pa0 = rp0.x*pwa.x + rp0.y*pwa.y + rp0.z*pwa.z + pwa.w;
                float pb0 = rp0.x*pwb.x + rp0.y*pwb.y + rp0.z*pwb.z + pwb.w;
                float pa1 = rp1.x*pwa.x + rp1.y*pwa.y + rp1.z*pwa.z + pwa.w;
                float pb1 = rp1.x*pwb.x + rp1.y*pwb.y + rp1.z*pwb.z + pwb.w;
                *(float2*)&es[r0 * ES + n] = make_float2(f2tf(fmaxf(acc[ntl][0] + pa0, 0.f)),
                                                         f2tf(fmaxf(acc[ntl][1] + pb0, 0.f)));
                *(float2*)&es[r1 * ES + n] = make_float2(f2tf(fmaxf(acc[ntl][2] + pa1, 0.f)),
                                                         f2tf(fmaxf(acc[ntl][3] + pb1, 0.f)));
            }
        }
        __syncthreads();   // rows now complete across both N-halves

        // layer 2
        #pragma unroll
        for (int ntl = 0; ntl < 8; ntl++)
            acc[ntl][0] = acc[ntl][1] = acc[ntl][2] = acc[ntl][3] = 0.f;
        wgemm_h(acc, es, w2s, mrow0, g, q, lid, hw);

        // epilogue2: max over this warp's 16 rows (= point p0+rw), +b2 -> g_agg (own N-half)
        {
            int p = p0 + rw;
            float* outp = g_agg + (size_t)p * CC;
            #pragma unroll
            for (int ntl = 0; ntl < 8; ntl++) {
                float m0 = fmaxf(acc[ntl][0], acc[ntl][2]);
                float m1 = fmaxf(acc[ntl][1], acc[ntl][3]);
                #pragma unroll
                for (int s = 4; s <= 16; s <<= 1) {
                    m0 = fmaxf(m0, __shfl_xor_sync(0xffffffffu, m0, s));
                    m1 = fmaxf(m1, __shfl_xor_sync(0xffffffffu, m1, s));
                }
                if (g == 0) {
                    int n = hw * 64 + ntl * 8 + q * 2;
                    *(float2*)&outp[n] = make_float2(m0 + eb2s[n], m1 + eb2s[n + 1]);
                }
            }
        }
    }
}

// ---------------- upd kernel: 512 threads, 256 points/CTA ----------------
#define UO_A    0
#define UO_W    33792
#define UO_B1   50176
#define UO_B2   50304
#define U_SMEMF 50432
#define U_SMEM  (U_SMEMF*4)

__global__ void __launch_bounds__(512) upd_kernel(
    const float* __restrict__ src, float* __restrict__ dst,
    const float* __restrict__ ub1, const float* __restrict__ ub2, int t) {
    extern __shared__ __align__(16) float sm[];
    float*  au   = sm + UO_A;
    float4* wbuf = (float4*)(sm + UO_W);
    float*  ub1s = sm + UO_B1;
    float*  ub2s = sm + UO_B2;

    const int tid = threadIdx.x, wid = tid >> 5, lid = tid & 31;
    const int g = lid >> 2, q = lid & 3;
    const int mrow0 = wid * 16;
    int p0 = blockIdx.x * 256;

    for (int r = wid; r < 256; r += 16) {
        const float4* a = (const float4*)(g_agg + (size_t)(p0 + r) * CC);
        *(float4*)&au[r * ES + lid * 4] = f2tf4(a[lid]);
    }
    for (int i = tid; i < 4096; i += 512) wbuf[i] = g_pkU1[t][0][i];
    if (tid < CC) { ub1s[tid] = ub1[t*CC + tid]; ub2s[tid] = ub2[t*CC + tid]; }
    __syncthreads();

    float acc[16][4];
    #pragma unroll
    for (int nt = 0; nt < 16; nt++)
        acc[nt][0] = acc[nt][1] = acc[nt][2] = acc[nt][3] = 0.f;
    wgemm(acc, au, wbuf, mrow0, g, q, lid);
    __syncthreads();

    for (int r = wid; r < 256; r += 16) {
        const float4* a = (const float4*)(src + (size_t)(p0 + r) * CC);
        *(float4*)&au[r * ES + lid * 4] = f2tf4(a[lid]);
    }
    for (int i = tid; i < 4096; i += 512) wbuf[i] = g_pkU1[t][1][i];
    __syncthreads();
    wgemm(acc, au, wbuf, mrow0, g, q, lid);

    {
        int r0 = mrow0 + g, r1 = r0 + 8;
        #pragma unroll
        for (int nt = 0; nt < 16; nt++) {
            int n = nt * 8 + q * 2;
            float b0 = ub1s[n], b1 = ub1s[n + 1];
            *(float2*)&au[r0 * ES + n] = make_float2(f2tf(fmaxf(acc[nt][0] + b0, 0.f)),
                                                     f2tf(fmaxf(acc[nt][1] + b1, 0.f)));
            *(float2*)&au[r1 * ES + n] = make_float2(f2tf(fmaxf(acc[nt][2] + b0, 0.f)),
                                                     f2tf(fmaxf(acc[nt][3] + b1, 0.f)));
        }
    }
    __syncthreads();

    for (int i = tid; i < 4096; i += 512) wbuf[i] = g_pkU2[t][i];
    __syncthreads();

    #pragma unroll
    for (int nt = 0; nt < 16; nt++)
        acc[nt][0] = acc[nt][1] = acc[nt][2] = acc[nt][3] = 0.f;
    wgemm(acc, au, wbuf, mrow0, g, q, lid);

    {
        int r0 = mrow0 + g, r1 = r0 + 8;
        const float* s0 = src + (size_t)(p0 + r0) * CC;
        const float* s1 = src + (size_t)(p0 + r1) * CC;
        float* d0 = dst + (size_t)(p0 + r0) * CC;
        float* d1 = dst + (size_t)(p0 + r1) * CC;
        #pragma unroll
        for (int nt = 0; nt < 16; nt++) {
            int n = nt * 8 + q * 2;
            float b0 = ub2s[n], b1 = ub2s[n + 1];
            float2 x0 = *(const float2*)&s0[n];
            float2 x1 = *(const float2*)&s1[n];
            *(float2*)&d0[n] = make_float2(acc[nt][0] + b0 + x0.x, acc[nt][1] + b1 + x0.y);
            *(float2*)&d1[n] = make_float2(acc[nt][2] + b0 + x1.x, acc[nt][3] + b1 + x1.y);
        }
    }
}

// ---------------- launch ----------------
extern "C" void kernel_launch(void* const* d_in, const int* in_sizes, int n_in,
                              void* d_out, int out_size) {
    const float* xyz      = (const float*)d_in[0];
    const float* features = (const float*)d_in[1];
    const int*   knn      = (const int*)  d_in[2];
    const float* off_W1   = (const float*)d_in[3];
    const float* off_b1   = (const float*)d_in[4];
    const float* off_W2   = (const float*)d_in[5];
    const float* off_b2   = (const float*)d_in[6];
    const float* edge_W1  = (const float*)d_in[7];
    const float* edge_b1  = (const float*)d_in[8];
    const float* edge_W2  = (const float*)d_in[9];
    const float* edge_b2  = (const float*)d_in[10];
    const float* upd_W1   = (const float*)d_in[11];
    const float* upd_b1   = (const float*)d_in[12];
    const float* upd_W2   = (const float*)d_in[13];
    const float* upd_b2   = (const float*)d_in[14];
    float* out = (float*)d_out;

    float *featA, *featB;
    cudaGetSymbolAddress((void**)&featA, g_featA);
    cudaGetSymbolAddress((void**)&featB, g_featB);

    cudaFuncSetAttribute(offset_kernel, cudaFuncAttributeMaxDynamicSharedMemorySize, O_SMEM);
    cudaFuncSetAttribute(edge_kernel,   cudaFuncAttributeMaxDynamicSharedMemorySize, E_SMEM);
    cudaFuncSetAttribute(upd_kernel,    cudaFuncAttributeMaxDynamicSharedMemorySize, U_SMEM);
    int nsm = 148;
    cudaDeviceGetAttribute(&nsm, cudaDevAttrMultiProcessorCount, 0);

    prep_kernel<<<128, 256>>>(off_W1, off_W2, edge_W1, edge_b1, edge_W2, upd_W1, upd_W2);

    const float* src = features;
    for (int t = 0; t < TT; t++) {
        float* dst = (t == TT-1) ? out : ((t == 0) ? featA : featB);
        offset_kernel<<<BN_/256, 512, O_SMEM>>>(src, xyz, off_b1, off_b2);
        edge_kernel<<<nsm, 512, E_SMEM>>>(src, xyz, knn, edge_b2, t);
        upd_kernel<<<BN_/256, 512, U_SMEM>>>(src, dst, upd_b1, upd_b2, t);
        src = dst;
    }
}

// round 10
// speedup vs baseline: 4.9734x; 1.0215x over previous
#include <cuda_runtime.h>
#include <cuda_bf16.h>
#include <cstdint>

#define BB 4
#define NN 8192
#define KK 16
#define CC 128
#define TT 3
#define BN_ (BB*NN)          // 32768 points
#define CE 131               // 3 + C
#define NTILES (BN_/8)       // 4096 edge tiles (8 points x 16 nbrs = 128 rows)
#define ES 132               // padded A row stride (floats) -> conflict-free frags

// ---------------- device scratch ----------------
__device__ __align__(16) float g_featA[BN_*CC];
__device__ __align__(16) float g_featB[BN_*CC];
__device__ __align__(16) float g_featTF[BN_*CC];  // tf32-rounded mirror of current features
__device__ __align__(16) float g_agg[BN_*CC];
__device__ float  g_center[BN_*3];
__device__ float4 g_posw[TT*CC];        // {w0,w1,w2,b1} per edge output n
// packed tf32 weight fragments: idx y in [0,4096): lid=y&31, nt=(y>>5)&15, p2=y>>9
// float4 = {W[n][16p2+q], W[n][16p2+q+4], W[n][16p2+q+8], W[n][16p2+q+12]}, n=nt*8+(lid>>2), q=lid&3
__device__ float4 g_pkE1[TT][4096];
__device__ float4 g_pkE2[TT][4096];
__device__ float4 g_pkU1[TT][2][4096];
__device__ float4 g_pkU2[TT][4096];
__device__ float4 g_pkO1[4096];
__device__ float4 g_pkO2[256];          // n8 fragment (rows 3..7 zero)

// ---------------- helpers ----------------
__device__ __forceinline__ float f2tf(float x) {
    uint32_t u; asm("cvt.rna.tf32.f32 %0, %1;" : "=r"(u) : "f"(x));
    return __uint_as_float(u);
}
__device__ __forceinline__ float4 f2tf4(float4 v) {
    v.x = f2tf(v.x); v.y = f2tf(v.y); v.z = f2tf(v.z); v.w = f2tf(v.w);
    return v;
}
__device__ __forceinline__ uint32_t s2u(const void* p) {
    uint32_t a;
    asm("{ .reg .u64 t; cvta.to.shared.u64 t, %1; cvt.u32.u64 %0, t; }" : "=r"(a) : "l"(p));
    return a;
}
__device__ __forceinline__ void cpasync16(uint32_t dst, const void* src) {
    asm volatile("cp.async.cg.shared.global [%0], [%1], 16;" :: "r"(dst), "l"(src));
}
#define CP_COMMIT() asm volatile("cp.async.commit_group;" ::: "memory")
#define CP_WAIT0()  asm volatile("cp.async.wait_group 0;" ::: "memory")

__device__ __forceinline__ void mma8(float* c, uint32_t a0, uint32_t a1,
                                     uint32_t a2, uint32_t a3,
                                     uint32_t b0, uint32_t b1) {
    asm volatile(
        "mma.sync.aligned.m16n8k8.row.col.f32.tf32.tf32.f32 "
        "{%0,%1,%2,%3}, {%4,%5,%6,%7}, {%8,%9}, {%0,%1,%2,%3};"
        : "+f"(c[0]), "+f"(c[1]), "+f"(c[2]), "+f"(c[3])
        : "r"(a0), "r"(a1), "r"(a2), "r"(a3), "r"(b0), "r"(b1));
}
__device__ __forceinline__ uint32_t ldu(const float* p) { return __float_as_uint(*p); }

// full warp GEMM: 16 rows x 128 N over K=128 (offset/upd).
__device__ __forceinline__ void wgemm(float acc[16][4], const float* __restrict__ abase,
                                      const float4* __restrict__ pb,
                                      int mrow0, int g, int q, int lid) {
    const float* ar0 = abase + (mrow0 + g) * ES + q;
    const float* ar1 = ar0 + 8 * ES;
    #pragma unroll
    for (int p2 = 0; p2 < 8; p2++) {
        int k0 = p2 * 16;
        uint32_t aE0 = ldu(ar0 + k0),      aE2 = ldu(ar0 + k0 + 4);
        uint32_t aE1 = ldu(ar1 + k0),      aE3 = ldu(ar1 + k0 + 4);
        uint32_t aO0 = ldu(ar0 + k0 + 8),  aO2 = ldu(ar0 + k0 + 12);
        uint32_t aO1 = ldu(ar1 + k0 + 8),  aO3 = ldu(ar1 + k0 + 12);
        const float4* pbl = pb + p2 * 512 + lid;
        #pragma unroll
        for (int nt = 0; nt < 16; nt++) {
            float4 w = pbl[nt * 32];
            mma8(acc[nt], aE0, aE1, aE2, aE3, __float_as_uint(w.x), __float_as_uint(w.y));
            mma8(acc[nt], aO0, aO1, aO2, aO3, __float_as_uint(w.z), __float_as_uint(w.w));
        }
    }
}

// edge warp GEMM: 32 rows (2x16 groups at row0) x 32 N (quarter nq) over K=128.
__device__ __forceinline__ void wgemm32(float acc[2][4][4], const float* __restrict__ abase,
                                        const float4* __restrict__ pb,
                                        int row0, int g, int q, int lid, int nq) {
    const float* a0 = abase + (row0 + g) * ES + q;
    #pragma unroll
    for (int p2 = 0; p2 < 8; p2++) {
        int k0 = p2 * 16;
        uint32_t E0[2], E1[2], E2[2], E3[2], O0[2], O1[2], O2[2], O3[2];
        #pragma unroll
        for (int mg = 0; mg < 2; mg++) {
            const float* r0p = a0 + mg * 16 * ES + k0;
            const float* r1p = r0p + 8 * ES;
            E0[mg] = ldu(r0p);      E2[mg] = ldu(r0p + 4);
            E1[mg] = ldu(r1p);      E3[mg] = ldu(r1p + 4);
            O0[mg] = ldu(r0p + 8);  O2[mg] = ldu(r0p + 12);
            O1[mg] = ldu(r1p + 8);  O3[mg] = ldu(r1p + 12);
        }
        const float4* pbl = pb + p2 * 512 + nq * 128 + lid;
        #pragma unroll
        for (int ntl = 0; ntl < 4; ntl++) {
            float4 w = pbl[ntl * 32];
            uint32_t b0 = __float_as_uint(w.x), b1 = __float_as_uint(w.y);
            uint32_t b2 = __float_as_uint(w.z), b3 = __float_as_uint(w.w);
            #pragma unroll
            for (int mg = 0; mg < 2; mg++) {
                mma8(acc[mg][ntl], E0[mg], E1[mg], E2[mg], E3[mg], b0, b1);
                mma8(acc[mg][ntl], O0[mg], O1[mg], O2[mg], O3[mg], b2, b3);
            }
        }
    }
}

// ---------------- prep ----------------
__global__ void prep_kernel(const float* __restrict__ features,
                            const float* __restrict__ off_W1, const float* __restrict__ off_W2,
                            const float* __restrict__ edge_W1, const float* __restrict__ edge_b1,
                            const float* __restrict__ edge_W2,
                            const float* __restrict__ upd_W1, const float* __restrict__ upd_W2) {
    int i0 = blockIdx.x * blockDim.x + threadIdx.x, st = gridDim.x * blockDim.x;
    for (int x = i0; x < BN_ * CC; x += st) g_featTF[x] = f2tf(features[x]);
    for (int x = i0; x < TT * 4096; x += st) {
        int t = x >> 12, y = x & 4095;
        int lid = y & 31, nt = (y >> 5) & 15, p2 = y >> 9;
        int n = nt * 8 + (lid >> 2), q = lid & 3, k = p2 * 16 + q;
        const float* s1 = edge_W1 + ((size_t)t * CC + n) * CE + 3;
        g_pkE1[t][y] = make_float4(f2tf(s1[k]), f2tf(s1[k+4]), f2tf(s1[k+8]), f2tf(s1[k+12]));
        const float* s2 = edge_W2 + ((size_t)t * CC + n) * CC;
        g_pkE2[t][y] = make_float4(f2tf(s2[k]), f2tf(s2[k+4]), f2tf(s2[k+8]), f2tf(s2[k+12]));
        const float* u1 = upd_W1 + ((size_t)t * CC + n) * 2 * CC;
        g_pkU1[t][0][y] = make_float4(f2tf(u1[k]), f2tf(u1[k+4]), f2tf(u1[k+8]), f2tf(u1[k+12]));
        const float* u1b = u1 + CC;
        g_pkU1[t][1][y] = make_float4(f2tf(u1b[k]), f2tf(u1b[k+4]), f2tf(u1b[k+8]), f2tf(u1b[k+12]));
        const float* u2 = upd_W2 + ((size_t)t * CC + n) * CC;
        g_pkU2[t][y] = make_float4(f2tf(u2[k]), f2tf(u2[k+4]), f2tf(u2[k+8]), f2tf(u2[k+12]));
    }
    for (int x = i0; x < 4096; x += st) {
        int lid = x & 31, nt = (x >> 5) & 15, p2 = x >> 9;
        int n = nt * 8 + (lid >> 2), q = lid & 3, k = p2 * 16 + q;
        const float* s = off_W1 + (size_t)n * CC;
        g_pkO1[x] = make_float4(f2tf(s[k]), f2tf(s[k+4]), f2tf(s[k+8]), f2tf(s[k+12]));
    }
    for (int x = i0; x < 256; x += st) {
        int lid = x & 31, p2 = x >> 5;
        int n = lid >> 2, q = lid & 3, k = p2 * 16 + q;
        if (n < 3) {
            const float* s = off_W2 + (size_t)n * CC;
            g_pkO2[x] = make_float4(f2tf(s[k]), f2tf(s[k+4]), f2tf(s[k+8]), f2tf(s[k+12]));
        } else {
            g_pkO2[x] = make_float4(0.f, 0.f, 0.f, 0.f);
        }
    }
    for (int x = i0; x < TT * CC; x += st) {
        int t = x >> 7, n = x & 127;
        const float* w = edge_W1 + ((size_t)t * CC + n) * CE;
        g_posw[x] = make_float4(w[0], w[1], w[2], edge_b1[t * CC + n]);
    }
}

// ---------------- offset kernel: tensor-core, 256 points/CTA ----------------
#define OO_F    0
#define OO_W1   33792
#define OO_W2   50176
#define OO_B1   51200
#define OO_B2   51328
#define O_SMEMF 51336
#define O_SMEM  (O_SMEMF*4)

__global__ void __launch_bounds__(512) offset_kernel(
    const float* __restrict__ feat, const float* __restrict__ xyz,
    const float* __restrict__ b1, const float* __restrict__ b2) {
    extern __shared__ __align__(16) float sm[];
    float*  fs  = sm + OO_F;
    float4* w1s = (float4*)(sm + OO_W1);
    float4* w2s = (float4*)(sm + OO_W2);
    float*  b1s = sm + OO_B1;
    float*  b2s = sm + OO_B2;

    const int tid = threadIdx.x, wid = tid >> 5, lid = tid & 31;
    const int g = lid >> 2, q = lid & 3;
    const int mrow0 = wid * 16;
    int p0 = blockIdx.x * 256;

    for (int i = tid; i < 4096; i += 512) w1s[i] = g_pkO1[i];
    if (tid < 256) w2s[tid] = g_pkO2[tid];
    if (tid < CC) b1s[tid] = b1[tid];
    if (tid < 3) b2s[tid] = b2[tid];
    for (int r = wid; r < 256; r += 16) {
        const float4* src = (const float4*)(feat + (size_t)(p0 + r) * CC);
        *(float4*)&fs[r * ES + lid * 4] = f2tf4(src[lid]);
    }
    __syncthreads();

    float acc[16][4];
    #pragma unroll
    for (int nt = 0; nt < 16; nt++)
        acc[nt][0] = acc[nt][1] = acc[nt][2] = acc[nt][3] = 0.f;
    wgemm(acc, fs, w1s, mrow0, g, q, lid);

    {
        int r0 = mrow0 + g, r1 = r0 + 8;
        #pragma unroll
        for (int nt = 0; nt < 16; nt++) {
            int n = nt * 8 + q * 2;
            float c0 = b1s[n], c1 = b1s[n + 1];
            *(float2*)&fs[r0 * ES + n] = make_float2(f2tf(fmaxf(acc[nt][0] + c0, 0.f)),
                                                     f2tf(fmaxf(acc[nt][1] + c1, 0.f)));
            *(float2*)&fs[r1 * ES + n] = make_float2(f2tf(fmaxf(acc[nt][2] + c0, 0.f)),
                                                     f2tf(fmaxf(acc[nt][3] + c1, 0.f)));
        }
    }

    float a2[4] = {0.f, 0.f, 0.f, 0.f};
    {
        const float* ar0 = fs + (mrow0 + g) * ES + q;
        const float* ar1 = ar0 + 8 * ES;
        #pragma unroll
        for (int p2 = 0; p2 < 8; p2++) {
            int k0 = p2 * 16;
            uint32_t aE0 = ldu(ar0 + k0),     aE2 = ldu(ar0 + k0 + 4);
            uint32_t aE1 = ldu(ar1 + k0),     aE3 = ldu(ar1 + k0 + 4);
            uint32_t aO0 = ldu(ar0 + k0 + 8), aO2 = ldu(ar0 + k0 + 12);
            uint32_t aO1 = ldu(ar1 + k0 + 8), aO3 = ldu(ar1 + k0 + 12);
            float4 w = w2s[p2 * 32 + lid];
            mma8(a2, aE0, aE1, aE2, aE3, __float_as_uint(w.x), __float_as_uint(w.y));
            mma8(a2, aO0, aO1, aO2, aO3, __float_as_uint(w.z), __float_as_uint(w.w));
        }
    }
    {
        int r0 = p0 + mrow0 + g, r1 = r0 + 8;
        if (q == 0) {
            g_center[r0*3 + 0] = xyz[r0*3 + 0] + a2[0] + b2s[0];
            g_center[r0*3 + 1] = xyz[r0*3 + 1] + a2[1] + b2s[1];
            g_center[r1*3 + 0] = xyz[r1*3 + 0] + a2[2] + b2s[0];
            g_center[r1*3 + 1] = xyz[r1*3 + 1] + a2[3] + b2s[1];
        } else if (q == 1) {
            g_center[r0*3 + 2] = xyz[r0*3 + 2] + a2[0] + b2s[2];
            g_center[r1*3 + 2] = xyz[r1*3 + 2] + a2[2] + b2s[2];
        }
    }
}

// ---------------- edge kernel: persistent, 512 threads, 32x32 warp tiles, cp.async gather ----
// smem floats: es[128*ES]=16896, w1 16384, w2 16384, relpos f4[128]=512, posw 512, eb2 128
#define EO_ES   0
#define EO_W1   16896
#define EO_W2   33280
#define EO_RP   49664
#define EO_PW   50176
#define EO_EB2  50688
#define E_SMEMF 50816
#define E_SMEM  (E_SMEMF*4)

__global__ void __launch_bounds__(512, 1) edge_kernel(
    const float* __restrict__ xyz, const int* __restrict__ knn,
    const float* __restrict__ eb2, int t) {
    extern __shared__ __align__(16) float sm[];
    float*  es   = sm + EO_ES;
    float4* w1s  = (float4*)(sm + EO_W1);
    float4* w2s  = (float4*)(sm + EO_W2);
    float4* relpos = (float4*)(sm + EO_RP);
    float4* posw   = (float4*)(sm + EO_PW);
    float*  eb2s   = sm + EO_EB2;

    const int tid = threadIdx.x, wid = tid >> 5, lid = tid & 31;
    const int g = lid >> 2, q = lid & 3;
    const int rw2 = wid & 3;         // row group of 32 (= 2 points)
    const int nq  = wid >> 2;        // N quarter
    const int row0 = rw2 * 32;
    const int grow = tid >> 2;       // gather row (0..127)
    const int seg  = tid & 3;        // 128B segment within row
    const uint32_t es_dst = s2u(es) + (uint32_t)(grow * ES + seg * 32) * 4;

    for (int i = tid; i < 4096; i += 512) { w1s[i] = g_pkE1[t][i]; w2s[i] = g_pkE2[t][i]; }
    if (tid < CC) { posw[tid] = g_posw[t * CC + tid]; eb2s[tid] = eb2[t * CC + tid]; }

    for (int tt = blockIdx.x; tt < NTILES; tt += gridDim.x) {
        int p0 = tt * 8;
        int base = p0 & ~(NN - 1);
        __syncthreads();   // previous tile's compute (and first-tile weight fill) complete

        // gather via cp.async from pre-rounded features
        {
            int idx = __ldg(&knn[(size_t)p0 * KK + grow]);
            const float* src = g_featTF + (size_t)(base + idx) * CC + seg * 32;
            #pragma unroll
            for (int j = 0; j < 8; j++)
                cpasync16(es_dst + j * 16, src + j * 4);
            CP_COMMIT();
        }
        if (tid < 128) {
            int r = tid, p = p0 + (r >> 4);
            int nb = base + __ldg(&knn[(size_t)p0 * KK + r]);
            float cx = g_center[p*3+0], cy = g_center[p*3+1], cz = g_center[p*3+2];
            relpos[r] = make_float4(xyz[nb*3+0]-cx, xyz[nb*3+1]-cy, xyz[nb*3+2]-cz, 0.f);
        }
        CP_WAIT0();
        __syncthreads();

        // layer 1 (feat part)
        float acc[2][4][4];
        #pragma unroll
        for (int mg = 0; mg < 2; mg++)
            #pragma unroll
            for (int ntl = 0; ntl < 4; ntl++)
                acc[mg][ntl][0] = acc[mg][ntl][1] = acc[mg][ntl][2] = acc[mg][ntl][3] = 0.f;
        wgemm32(acc, es, w1s, row0, g, q, lid, nq);

        // epilogue1: + rel_pos·W + b1 (exact fp32), ReLU, tf32 -> own rows/cols
        #pragma unroll
        for (int mg = 0; mg < 2; mg++) {
            int r0 = row0 + mg * 16 + g, r1 = r0 + 8;
            float4 rp0 = relpos[r0], rp1 = relpos[r1];
            #pragma unroll
            for (int ntl = 0; ntl < 4; ntl++) {
                int n = nq * 32 + ntl * 8 + q * 2;
                float4 pwa = posw[n], pwb = posw[n + 1];
                float pa0 = rp0.x*pwa.x + rp0.y*pwa.y + rp0.z*pwa.z + pwa.w;
                float pb0 = rp0.x*pwb.x + rp0.y*pwb.y + rp0.z*pwb.z + pwb.w;
                float pa1 = rp1.x*pwa.x + rp1.y*pwa.y + rp1.z*pwa.z + pwa.w;
                float pb1 = rp1.x*pwb.x + rp1.y*pwb.y + rp1.z*pwb.z + pwb.w;
                *(float2*)&es[r0 * ES + n] = make_float2(f2tf(fmaxf(acc[mg][ntl][0] + pa0, 0.f)),
                                                         f2tf(fmaxf(acc[mg][ntl][1] + pb0, 0.f)));
                *(float2*)&es[r1 * ES + n] = make_float2(f2tf(fmaxf(acc[mg][ntl][2] + pa1, 0.f)),
                                                         f2tf(fmaxf(acc[mg][ntl][3] + pb1, 0.f)));
            }
        }
        __syncthreads();

        // layer 2
        #pragma unroll
        for (int mg = 0; mg < 2; mg++)
            #pragma unroll
            for (int ntl = 0; ntl < 4; ntl++)
                acc[mg][ntl][0] = acc[mg][ntl][1] = acc[mg][ntl][2] = acc[mg][ntl][3] = 0.f;
        wgemm32(acc, es, w2s, row0, g, q, lid, nq);

        // epilogue2: per mg-group = one point's 16 neighbor rows -> max, +b2
        #pragma unroll
        for (int mg = 0; mg < 2; mg++) {
            int p = p0 + rw2 * 2 + mg;
            float* outp = g_agg + (size_t)p * CC;
            #pragma unroll
            for (int ntl = 0; ntl < 4; ntl++) {
                float m0 = fmaxf(acc[mg][ntl][0], acc[mg][ntl][2]);
                float m1 = fmaxf(acc[mg][ntl][1], acc[mg][ntl][3]);
                #pragma unroll
                for (int s = 4; s <= 16; s <<= 1) {
                    m0 = fmaxf(m0, __shfl_xor_sync(0xffffffffu, m0, s));
                    m1 = fmaxf(m1, __shfl_xor_sync(0xffffffffu, m1, s));
                }
                if (g == 0) {
                    int n = nq * 32 + ntl * 8 + q * 2;
                    *(float2*)&outp[n] = make_float2(m0 + eb2s[n], m1 + eb2s[n + 1]);
                }
            }
        }
    }
}

// ---------------- upd kernel: 512 threads, 256 points/CTA ----------------
#define UO_A    0
#define UO_W    33792
#define UO_B1   50176
#define UO_B2   50304
#define U_SMEMF 50432
#define U_SMEM  (U_SMEMF*4)

__global__ void __launch_bounds__(512) upd_kernel(
    const float* __restrict__ src, float* __restrict__ dst,
    const float* __restrict__ ub1, const float* __restrict__ ub2, int t) {
    extern __shared__ __align__(16) float sm[];
    float*  au   = sm + UO_A;
    float4* wbuf = (float4*)(sm + UO_W);
    float*  ub1s = sm + UO_B1;
    float*  ub2s = sm + UO_B2;

    const int tid = threadIdx.x, wid = tid >> 5, lid = tid & 31;
    const int g = lid >> 2, q = lid & 3;
    const int mrow0 = wid * 16;
    int p0 = blockIdx.x * 256;

    for (int r = wid; r < 256; r += 16) {
        const float4* a = (const float4*)(g_agg + (size_t)(p0 + r) * CC);
        *(float4*)&au[r * ES + lid * 4] = f2tf4(a[lid]);
    }
    for (int i = tid; i < 4096; i += 512) wbuf[i] = g_pkU1[t][0][i];
    if (tid < CC) { ub1s[tid] = ub1[t*CC + tid]; ub2s[tid] = ub2[t*CC + tid]; }
    __syncthreads();

    float acc[16][4];
    #pragma unroll
    for (int nt = 0; nt < 16; nt++)
        acc[nt][0] = acc[nt][1] = acc[nt][2] = acc[nt][3] = 0.f;
    wgemm(acc, au, wbuf, mrow0, g, q, lid);
    __syncthreads();

    for (int r = wid; r < 256; r += 16) {
        const float4* a = (const float4*)(src + (size_t)(p0 + r) * CC);
        *(float4*)&au[r * ES + lid * 4] = f2tf4(a[lid]);
    }
    for (int i = tid; i < 4096; i += 512) wbuf[i] = g_pkU1[t][1][i];
    __syncthreads();
    wgemm(acc, au, wbuf, mrow0, g, q, lid);

    {
        int r0 = mrow0 + g, r1 = r0 + 8;
        #pragma unroll
        for (int nt = 0; nt < 16; nt++) {
            int n = nt * 8 + q * 2;
            float b0 = ub1s[n], b1 = ub1s[n + 1];
            *(float2*)&au[r0 * ES + n] = make_float2(f2tf(fmaxf(acc[nt][0] + b0, 0.f)),
                                                     f2tf(fmaxf(acc[nt][1] + b1, 0.f)));
            *(float2*)&au[r1 * ES + n] = make_float2(f2tf(fmaxf(acc[nt][2] + b0, 0.f)),
                                                     f2tf(fmaxf(acc[nt][3] + b1, 0.f)));
        }
    }
    __syncthreads();

    for (int i = tid; i < 4096; i += 512) wbuf[i] = g_pkU2[t][i];
    __syncthreads();

    #pragma unroll
    for (int nt = 0; nt < 16; nt++)
        acc[nt][0] = acc[nt][1] = acc[nt][2] = acc[nt][3] = 0.f;
    wgemm(acc, au, wbuf, mrow0, g, q, lid);

    {
        int r0 = mrow0 + g, r1 = r0 + 8;
        const float* s0 = src + (size_t)(p0 + r0) * CC;
        const float* s1 = src + (size_t)(p0 + r1) * CC;
        float* d0 = dst + (size_t)(p0 + r0) * CC;
        float* d1 = dst + (size_t)(p0 + r1) * CC;
        float* t0 = g_featTF + (size_t)(p0 + r0) * CC;
        float* t1 = g_featTF + (size_t)(p0 + r1) * CC;
        #pragma unroll
        for (int nt = 0; nt < 16; nt++) {
            int n = nt * 8 + q * 2;
            float b0 = ub2s[n], b1 = ub2s[n + 1];
            float2 x0 = *(const float2*)&s0[n];
            float2 x1 = *(const float2*)&s1[n];
            float2 v0 = make_float2(acc[nt][0] + b0 + x0.x, acc[nt][1] + b1 + x0.y);
            float2 v1 = make_float2(acc[nt][2] + b0 + x1.x, acc[nt][3] + b1 + x1.y);
            *(float2*)&d0[n] = v0;
            *(float2*)&d1[n] = v1;
            *(float2*)&t0[n] = make_float2(f2tf(v0.x), f2tf(v0.y));
            *(float2*)&t1[n] = make_float2(f2tf(v1.x), f2tf(v1.y));
        }
    }
}

// ---------------- launch ----------------
extern "C" void kernel_launch(void* const* d_in, const int* in_sizes, int n_in,
                              void* d_out, int out_size) {
    const float* xyz      = (const float*)d_in[0];
    const float* features = (const float*)d_in[1];
    const int*   knn      = (const int*)  d_in[2];
    const float* off_W1   = (const float*)d_in[3];
    const float* off_b1   = (const float*)d_in[4];
    const float* off_W2   = (const float*)d_in[5];
    const float* off_b2   = (const float*)d_in[6];
    const float* edge_W1  = (const float*)d_in[7];
    const float* edge_b1  = (const float*)d_in[8];
    const float* edge_W2  = (const float*)d_in[9];
    const float* edge_b2  = (const float*)d_in[10];
    const float* upd_W1   = (const float*)d_in[11];
    const float* upd_b1   = (const float*)d_in[12];
    const float* upd_W2   = (const float*)d_in[13];
    const float* upd_b2   = (const float*)d_in[14];
    float* out = (float*)d_out;

    float *featA, *featB;
    cudaGetSymbolAddress((void**)&featA, g_featA);
    cudaGetSymbolAddress((void**)&featB, g_featB);

    cudaFuncSetAttribute(offset_kernel, cudaFuncAttributeMaxDynamicSharedMemorySize, O_SMEM);
    cudaFuncSetAttribute(edge_kernel,   cudaFuncAttributeMaxDynamicSharedMemorySize, E_SMEM);
    cudaFuncSetAttribute(upd_kernel,    cudaFuncAttributeMaxDynamicSharedMemorySize, U_SMEM);
    int nsm = 148;
    cudaDeviceGetAttribute(&nsm, cudaDevAttrMultiProcessorCount, 0);

    prep_kernel<<<256, 256>>>(features, off_W1, off_W2, edge_W1, edge_b1, edge_W2,
                              upd_W1, upd_W2);

    const float* src = features;
    for (int t = 0; t < TT; t++) {
        float* dst = (t == TT-1) ? out : ((t == 0) ? featA : featB);
        offset_kernel<<<BN_/256, 512, O_SMEM>>>(src, xyz, off_b1, off_b2);
        edge_kernel<<<nsm, 512, E_SMEM>>>(xyz, knn, edge_b2, t);
        upd_kernel<<<BN_/256, 512, U_SMEM>>>(src, dst, upd_b1, upd_b2, t);
        src = dst;
    }
}